// round 10
// baseline (speedup 1.0000x reference)
#include <cuda_runtime.h>
#include <cuda_bf16.h>
#include <math.h>
#include <stdint.h>

// Problem constants
#define BS      2
#define SEQ     2048
#define DMODEL  1024
#define HEADS   16
#define DK      64
#define MROWS   (BS * SEQ)                  // 4096
#define QKV_ELEMS (BS * HEADS * SEQ * DK)   // 4,194,304

// ---------------------------------------------------------------------------
// Device scratch (allocation-free rule)
// ---------------------------------------------------------------------------
__device__ __align__(16) __nv_bfloat16 g_Qh[QKV_ELEMS];
__device__ __align__(16) __nv_bfloat16 g_Ql[QKV_ELEMS];
__device__ __align__(16) __nv_bfloat16 g_Kh[QKV_ELEMS];
__device__ __align__(16) __nv_bfloat16 g_Kl[QKV_ELEMS];
__device__ __align__(16) __nv_bfloat16 g_Vh[QKV_ELEMS];   // [bh][d][s] transposed
__device__ __align__(16) __nv_bfloat16 g_Vl[QKV_ELEMS];   // [bh][d][s] transposed
__device__ __align__(16) __nv_bfloat16 g_Axh[3][MROWS * DMODEL];  // q/k/v input splits
__device__ __align__(16) __nv_bfloat16 g_Axl[3][MROWS * DMODEL];
__device__ __align__(16) __nv_bfloat16 g_Wsh[4][DMODEL * DMODEL]; // Wq/Wk/Wv/Wo splits
__device__ __align__(16) __nv_bfloat16 g_Wsl[4][DMODEL * DMODEL];
__device__ __align__(16) __nv_bfloat16 g_Sh[MROWS * DMODEL];      // scores split (concat)
__device__ __align__(16) __nv_bfloat16 g_Sl[MROWS * DMODEL];

// ---------------------------------------------------------------------------
// Helpers
// ---------------------------------------------------------------------------
__device__ __forceinline__ uint32_t smem_u32(const void* p) {
    uint32_t a;
    asm("{ .reg .u64 t; cvta.to.shared.u64 t, %1; cvt.u32.u64 %0, t; }" : "=r"(a) : "l"(p));
    return a;
}
__device__ __forceinline__ uint32_t lds32(uint32_t addr) {
    uint32_t v;
    asm volatile("ld.shared.b32 %0, [%1];" : "=r"(v) : "r"(addr));
    return v;
}
__device__ __forceinline__ void cp_async16(uint32_t saddr, const void* gaddr) {
    asm volatile("cp.async.cg.shared.global [%0], [%1], 16;" :: "r"(saddr), "l"(gaddr));
}
#define CP_COMMIT() asm volatile("cp.async.commit_group;" ::: "memory")
#define CP_WAIT(n)  asm volatile("cp.async.wait_group %0;" :: "n"(n) : "memory")

// D = A(16x16) * B(16x8) + D, bf16 inputs, fp32 accum
__device__ __forceinline__ void mma16816(float* c, const uint32_t* a, const uint32_t* b) {
    asm volatile(
        "mma.sync.aligned.m16n8k16.row.col.f32.bf16.bf16.f32 "
        "{%0,%1,%2,%3}, {%4,%5,%6,%7}, {%8,%9}, {%0,%1,%2,%3};"
        : "+f"(c[0]), "+f"(c[1]), "+f"(c[2]), "+f"(c[3])
        : "r"(a[0]), "r"(a[1]), "r"(a[2]), "r"(a[3]), "r"(b[0]), "r"(b[1]));
}
__device__ __forceinline__ void split1(float v, __nv_bfloat16& h, __nv_bfloat16& l) {
    h = __float2bfloat16(v);
    l = __float2bfloat16(v - __bfloat162float(h));
}

// ---------------------------------------------------------------------------
// Fused fp32 -> bf16 hi/lo split (up to 4 independent arrays, grid.y selects)
// ---------------------------------------------------------------------------
struct SplitP {
    const float* src[4];
    __nv_bfloat16* hi[4];
    __nv_bfloat16* lo[4];
};

__global__ __launch_bounds__(256) void split_many_kernel(SplitP p, int n4)
{
    int i = blockIdx.x * blockDim.x + threadIdx.x;
    if (i >= n4) return;
    const int which = blockIdx.y;
    const float* __restrict__ src = p.src[which];
    __nv_bfloat16* __restrict__ hi = p.hi[which];
    __nv_bfloat16* __restrict__ lo = p.lo[which];

    int e = i * 4;
    float4 f = reinterpret_cast<const float4*>(src)[i];
    __nv_bfloat16 h0, h1, h2, h3, l0, l1, l2, l3;
    split1(f.x, h0, l0); split1(f.y, h1, l1);
    split1(f.z, h2, l2); split1(f.w, h3, l3);
    __nv_bfloat162 hp0 = __halves2bfloat162(h0, h1), hp1 = __halves2bfloat162(h2, h3);
    __nv_bfloat162 lp0 = __halves2bfloat162(l0, l1), lp1 = __halves2bfloat162(l2, l3);
    uint2 hv, lv;
    hv.x = *reinterpret_cast<uint32_t*>(&hp0); hv.y = *reinterpret_cast<uint32_t*>(&hp1);
    lv.x = *reinterpret_cast<uint32_t*>(&lp0); lv.y = *reinterpret_cast<uint32_t*>(&lp1);
    *reinterpret_cast<uint2*>(hi + e) = hv;
    *reinterpret_cast<uint2*>(lo + e) = lv;
}

// ---------------------------------------------------------------------------
// Shared GEMM mainloop (identical math to the R8-passing kernel):
//   acc = Ah·Wh + Ah·Wl + Al·Wh   over K=1024, BK=32, CTA 128x128, 8 warps.
// ---------------------------------------------------------------------------
#define SA        40
#define TILE_B    (128 * SA * 2)
#define BUF_B     (4 * TILE_B)
#define GEMM_SMEM (2 * BUF_B)            // 81920 bytes

__device__ __forceinline__ void gemm_core(
    const __nv_bfloat16* __restrict__ Ah, const __nv_bfloat16* __restrict__ Al,
    const __nv_bfloat16* __restrict__ Wh, const __nv_bfloat16* __restrict__ Wl,
    uint32_t sb, int m0, int n0, int tid, float acc[4][4][4])
{
    const int lane = tid & 31;
    const int wid  = tid >> 5;
    const int wm   = wid >> 2;
    const int wn   = wid & 3;
    const int g    = lane >> 2;
    const int t4   = lane & 3;
    const int lr0 = tid >> 2;
    const int lc0 = (tid & 3) * 8;

#pragma unroll
    for (int mt = 0; mt < 4; mt++)
#pragma unroll
        for (int nt = 0; nt < 4; nt++)
#pragma unroll
            for (int q = 0; q < 4; q++) acc[mt][nt][q] = 0.f;

    auto load_tile = [&](int buf, int k0) {
        uint32_t base = sb + buf * BUF_B;
#pragma unroll
        for (int it = 0; it < 2; it++) {
            int r = lr0 + it * 64;
            uint32_t soff = (uint32_t)(r * SA + lc0) * 2;
            size_t ga = (size_t)(m0 + r) * DMODEL + k0 + lc0;
            size_t gb = (size_t)(n0 + r) * DMODEL + k0 + lc0;
            cp_async16(base + 0 * TILE_B + soff, Ah + ga);
            cp_async16(base + 1 * TILE_B + soff, Al + ga);
            cp_async16(base + 2 * TILE_B + soff, Wh + gb);
            cp_async16(base + 3 * TILE_B + soff, Wl + gb);
        }
        CP_COMMIT();
    };

    load_tile(0, 0);

    const int NT = DMODEL / 32;
    for (int kt = 0; kt < NT; kt++) {
        const int buf = kt & 1;
        if (kt + 1 < NT) {
            load_tile(buf ^ 1, (kt + 1) * 32);
            CP_WAIT(1);
        } else {
            CP_WAIT(0);
        }
        __syncthreads();

        const uint32_t bA = sb + buf * BUF_B;
        const uint32_t bB = bA + 2 * TILE_B;

#pragma unroll
        for (int s = 0; s < 2; s++) {
            const int kc = s * 16 + t4 * 2;
            uint32_t ah[4][4], al[4][4];
#pragma unroll
            for (int mt = 0; mt < 4; mt++) {
                int row = wm * 64 + mt * 16 + g;
                uint32_t o00 = (uint32_t)(row * SA + kc) * 2;
                uint32_t o10 = o00 + 8 * SA * 2;
                ah[mt][0] = lds32(bA + o00);
                ah[mt][1] = lds32(bA + o10);
                ah[mt][2] = lds32(bA + o00 + 16);
                ah[mt][3] = lds32(bA + o10 + 16);
                al[mt][0] = lds32(bA + TILE_B + o00);
                al[mt][1] = lds32(bA + TILE_B + o10);
                al[mt][2] = lds32(bA + TILE_B + o00 + 16);
                al[mt][3] = lds32(bA + TILE_B + o10 + 16);
            }
            uint32_t bh[4][2], bl[4][2];
#pragma unroll
            for (int nt = 0; nt < 4; nt++) {
                int n = wn * 32 + nt * 8 + g;
                uint32_t o = (uint32_t)(n * SA + kc) * 2;
                bh[nt][0] = lds32(bB + o);
                bh[nt][1] = lds32(bB + o + 16);
                bl[nt][0] = lds32(bB + TILE_B + o);
                bl[nt][1] = lds32(bB + TILE_B + o + 16);
            }
#pragma unroll
            for (int mt = 0; mt < 4; mt++)
#pragma unroll
                for (int nt = 0; nt < 4; nt++) {
                    mma16816(acc[mt][nt], ah[mt], bh[nt]);
                    mma16816(acc[mt][nt], ah[mt], bl[nt]);
                    mma16816(acc[mt][nt], al[mt], bh[nt]);
                }
        }
        __syncthreads();
    }
}

// ---------------------------------------------------------------------------
// QKV projection GEMM: one launch, grid.z in {0=Q, 1=K, 2=V}.
// mode 1: bf16 hi/lo split, head-split [bh][s][d]   (Q: scale 0.125, K)
// mode 2: bf16 hi/lo split, transposed [bh][d][s]   (V)
// ---------------------------------------------------------------------------
struct GemmZP {
    const __nv_bfloat16 *Ah[3], *Al[3], *Wh[3], *Wl[3];
    const float* bias[3];
    __nv_bfloat16 *Ch[3], *Cl[3];
    float scale[3];
    int mode[3];
};

__global__ __launch_bounds__(256) void gemm_qkv_kernel(GemmZP p)
{
    extern __shared__ __align__(128) char smem[];
    const uint32_t sb = smem_u32(smem);
    const int z = blockIdx.z;
    const int tid = threadIdx.x;
    const int lane = tid & 31;
    const int wid  = tid >> 5;
    const int wm = wid >> 2, wn = wid & 3;
    const int g = lane >> 2, t4 = lane & 3;
    const int m0 = blockIdx.y * 128;
    const int n0 = blockIdx.x * 128;

    float acc[4][4][4];
    gemm_core(p.Ah[z], p.Al[z], p.Wh[z], p.Wl[z], sb, m0, n0, tid, acc);

    const float* bias = p.bias[z];
    __nv_bfloat16* Ch = p.Ch[z];
    __nv_bfloat16* Cl = p.Cl[z];
    const float scale = p.scale[z];
    const int mode = p.mode[z];

#pragma unroll
    for (int mt = 0; mt < 4; mt++) {
        int row0 = m0 + wm * 64 + mt * 16 + g;
#pragma unroll
        for (int nt = 0; nt < 4; nt++) {
            int col = n0 + wn * 32 + nt * 8 + t4 * 2;
            float2 bv = *reinterpret_cast<const float2*>(bias + col);
            float v[2][2];
            v[0][0] = (acc[mt][nt][0] + bv.x) * scale;
            v[0][1] = (acc[mt][nt][1] + bv.y) * scale;
            v[1][0] = (acc[mt][nt][2] + bv.x) * scale;
            v[1][1] = (acc[mt][nt][3] + bv.y) * scale;
            int h = col >> 6, d = col & 63;
#pragma unroll
            for (int rr = 0; rr < 2; rr++) {
                int row = row0 + rr * 8;
                int b = row >> 11, s = row & 2047;
                int bh = b * HEADS + h;
                __nv_bfloat16 h0, h1, l0, l1;
                split1(v[rr][0], h0, l0);
                split1(v[rr][1], h1, l1);
                if (mode == 1) {
                    size_t off = ((size_t)bh * SEQ + s) * DK + d;
                    __nv_bfloat162 hp = __halves2bfloat162(h0, h1);
                    __nv_bfloat162 lp = __halves2bfloat162(l0, l1);
                    *reinterpret_cast<uint32_t*>(Ch + off) = *reinterpret_cast<uint32_t*>(&hp);
                    *reinterpret_cast<uint32_t*>(Cl + off) = *reinterpret_cast<uint32_t*>(&lp);
                } else {   // mode 2: V transposed [bh][d][s]
                    size_t o0 = ((size_t)bh * DK + d) * SEQ + s;
                    size_t o1 = ((size_t)bh * DK + d + 1) * SEQ + s;
                    Ch[o0] = h0; Ch[o1] = h1;
                    Cl[o0] = l0; Cl[o1] = l1;
                }
            }
        }
    }
}

// ---------------------------------------------------------------------------
// Output projection GEMM (fp32 out, row-major)
// ---------------------------------------------------------------------------
__global__ __launch_bounds__(256) void gemm_o_kernel(
    const __nv_bfloat16* __restrict__ Ah, const __nv_bfloat16* __restrict__ Al,
    const __nv_bfloat16* __restrict__ Wh, const __nv_bfloat16* __restrict__ Wl,
    const float* __restrict__ bias, float* __restrict__ Cf)
{
    extern __shared__ __align__(128) char smem[];
    const uint32_t sb = smem_u32(smem);
    const int tid = threadIdx.x;
    const int lane = tid & 31;
    const int wid  = tid >> 5;
    const int wm = wid >> 2, wn = wid & 3;
    const int g = lane >> 2, t4 = lane & 3;
    const int m0 = blockIdx.y * 128;
    const int n0 = blockIdx.x * 128;

    float acc[4][4][4];
    gemm_core(Ah, Al, Wh, Wl, sb, m0, n0, tid, acc);

#pragma unroll
    for (int mt = 0; mt < 4; mt++) {
        int row0 = m0 + wm * 64 + mt * 16 + g;
#pragma unroll
        for (int nt = 0; nt < 4; nt++) {
            int col = n0 + wn * 32 + nt * 8 + t4 * 2;
            float2 bv = *reinterpret_cast<const float2*>(bias + col);
            *reinterpret_cast<float2*>(Cf + (size_t)row0 * DMODEL + col) =
                make_float2(acc[mt][nt][0] + bv.x, acc[mt][nt][1] + bv.y);
            *reinterpret_cast<float2*>(Cf + (size_t)(row0 + 8) * DMODEL + col) =
                make_float2(acc[mt][nt][2] + bv.x, acc[mt][nt][3] + bv.y);
        }
    }
}

// ---------------------------------------------------------------------------
// Tensor-core flash attention (3-pass bf16 split, fp32 softmax) — R8-identical.
// ---------------------------------------------------------------------------
#define ATT_SA    72
#define ATT_TILE  (64 * ATT_SA * 2)
#define ATT_BUF   (4 * ATT_TILE)
#define ATT_SMEM  (2 * ATT_BUF)            // 73728 B

__global__ __launch_bounds__(256) void attn_mma_kernel(
    float* __restrict__ scores,
    __nv_bfloat16* __restrict__ Ao_h, __nv_bfloat16* __restrict__ Ao_l)
{
    extern __shared__ __align__(128) char asmem[];
    const uint32_t sb = smem_u32(asmem);

    const int tid  = threadIdx.x;
    const int lane = tid & 31;
    const int wid  = tid >> 5;
    const int g    = lane >> 2;
    const int t4   = lane & 3;

    const int bh = blockIdx.y;
    const int q0 = blockIdx.x * 128;
    const int qr = q0 + wid * 16;

    uint32_t qh[4][4], ql[4][4];
    {
        const uint32_t* Qh32 = reinterpret_cast<const uint32_t*>(
            g_Qh + ((size_t)bh * SEQ + qr) * DK);
        const uint32_t* Ql32 = reinterpret_cast<const uint32_t*>(
            g_Ql + ((size_t)bh * SEQ + qr) * DK);
#pragma unroll
        for (int kf = 0; kf < 4; kf++) {
            int c0 = kf * 8 + t4;
            qh[kf][0] = Qh32[g * 32 + c0];
            qh[kf][1] = Qh32[(g + 8) * 32 + c0];
            qh[kf][2] = Qh32[g * 32 + c0 + 4];
            qh[kf][3] = Qh32[(g + 8) * 32 + c0 + 4];
            ql[kf][0] = Ql32[g * 32 + c0];
            ql[kf][1] = Ql32[(g + 8) * 32 + c0];
            ql[kf][2] = Ql32[g * 32 + c0 + 4];
            ql[kf][3] = Ql32[(g + 8) * 32 + c0 + 4];
        }
    }

    float o[8][4];
#pragma unroll
    for (int dt = 0; dt < 8; dt++)
#pragma unroll
        for (int q = 0; q < 4; q++) o[dt][q] = 0.f;
    float mrow[2] = {-INFINITY, -INFINITY};
    float lrow[2] = {0.f, 0.f};

    auto load_chunk = [&](int buf, int kt) {
        uint32_t base = sb + buf * ATT_BUF;
#pragma unroll
        for (int it = 0; it < 2; it++) {
            int idx = tid + it * 256;
            int row = idx >> 3, c8 = idx & 7;
            uint32_t so = (uint32_t)row * (ATT_SA * 2) + c8 * 16;
            size_t gk = ((size_t)bh * SEQ + kt * 64 + row) * DK + c8 * 8;
            cp_async16(base + so, g_Kh + gk);
            cp_async16(base + ATT_TILE + so, g_Kl + gk);
            size_t gv = ((size_t)bh * DK + row) * SEQ + kt * 64 + c8 * 8;
            cp_async16(base + 2 * ATT_TILE + so, g_Vh + gv);
            cp_async16(base + 3 * ATT_TILE + so, g_Vl + gv);
        }
        CP_COMMIT();
    };

    load_chunk(0, 0);

    const int NCH = SEQ / 64;   // 32
    for (int kt = 0; kt < NCH; kt++) {
        const int buf = kt & 1;
        if (kt + 1 < NCH) {
            load_chunk(buf ^ 1, kt + 1);
            CP_WAIT(1);
        } else {
            CP_WAIT(0);
        }
        __syncthreads();

        const uint32_t bK  = sb + buf * ATT_BUF;
        const uint32_t bKl = bK + ATT_TILE;
        const uint32_t bV  = bK + 2 * ATT_TILE;
        const uint32_t bVl = bK + 3 * ATT_TILE;

        float s[8][4];
#pragma unroll
        for (int nt = 0; nt < 8; nt++)
#pragma unroll
            for (int q = 0; q < 4; q++) s[nt][q] = 0.f;
#pragma unroll
        for (int kf = 0; kf < 4; kf++) {
#pragma unroll
            for (int nt = 0; nt < 8; nt++) {
                uint32_t off = ((uint32_t)(nt * 8 + g) * ATT_SA + kf * 16 + t4 * 2) * 2;
                uint32_t kbh[2] = { lds32(bK + off),  lds32(bK + off + 16) };
                uint32_t kbl[2] = { lds32(bKl + off), lds32(bKl + off + 16) };
                mma16816(s[nt], qh[kf], kbh);
                mma16816(s[nt], qh[kf], kbl);
                mma16816(s[nt], ql[kf], kbh);
            }
        }

#pragma unroll
        for (int hh = 0; hh < 2; hh++) {
            float mx = -INFINITY;
#pragma unroll
            for (int nt = 0; nt < 8; nt++)
                mx = fmaxf(mx, fmaxf(s[nt][2 * hh], s[nt][2 * hh + 1]));
            mx = fmaxf(mx, __shfl_xor_sync(0xffffffffu, mx, 1));
            mx = fmaxf(mx, __shfl_xor_sync(0xffffffffu, mx, 2));
            float mnew = fmaxf(mrow[hh], mx);
            float sc = __expf(mrow[hh] - mnew);
            mrow[hh] = mnew;
            float rs = 0.f;
#pragma unroll
            for (int nt = 0; nt < 8; nt++) {
                s[nt][2 * hh]     = __expf(s[nt][2 * hh] - mnew);
                s[nt][2 * hh + 1] = __expf(s[nt][2 * hh + 1] - mnew);
                rs += s[nt][2 * hh] + s[nt][2 * hh + 1];
            }
            rs += __shfl_xor_sync(0xffffffffu, rs, 1);
            rs += __shfl_xor_sync(0xffffffffu, rs, 2);
            lrow[hh] = lrow[hh] * sc + rs;
#pragma unroll
            for (int dt = 0; dt < 8; dt++) {
                o[dt][2 * hh]     *= sc;
                o[dt][2 * hh + 1] *= sc;
            }
        }

        uint32_t ph[4][4], pl[4][4];
#pragma unroll
        for (int kf = 0; kf < 4; kf++) {
#pragma unroll
            for (int half = 0; half < 2; half++) {
                const float* sv = s[2 * kf + half];
                __nv_bfloat16 h0, h1, h2, h3, l0, l1, l2, l3;
                split1(sv[0], h0, l0); split1(sv[1], h1, l1);
                split1(sv[2], h2, l2); split1(sv[3], h3, l3);
                __nv_bfloat162 a, b, c, d;
                a = __halves2bfloat162(h0, h1); b = __halves2bfloat162(h2, h3);
                c = __halves2bfloat162(l0, l1); d = __halves2bfloat162(l2, l3);
                ph[kf][2 * half + 0] = *reinterpret_cast<uint32_t*>(&a);
                ph[kf][2 * half + 1] = *reinterpret_cast<uint32_t*>(&b);
                pl[kf][2 * half + 0] = *reinterpret_cast<uint32_t*>(&c);
                pl[kf][2 * half + 1] = *reinterpret_cast<uint32_t*>(&d);
            }
        }

#pragma unroll
        for (int kf = 0; kf < 4; kf++) {
#pragma unroll
            for (int dt = 0; dt < 8; dt++) {
                uint32_t off = ((uint32_t)(dt * 8 + g) * ATT_SA + kf * 16 + t4 * 2) * 2;
                uint32_t vbh[2] = { lds32(bV + off),  lds32(bV + off + 16) };
                uint32_t vbl[2] = { lds32(bVl + off), lds32(bVl + off + 16) };
                mma16816(o[dt], ph[kf], vbh);
                mma16816(o[dt], ph[kf], vbl);
                mma16816(o[dt], pl[kf], vbh);
            }
        }
        __syncthreads();
    }

    const int b = bh >> 4, hhd = bh & 15;
#pragma unroll
    for (int hh = 0; hh < 2; hh++) {
        float inv = 1.f / lrow[hh];
        int srow = qr + g + hh * 8;
#pragma unroll
        for (int dt = 0; dt < 8; dt++) {
            int d = dt * 8 + t4 * 2;
            float v0 = o[dt][2 * hh] * inv;
            float v1 = o[dt][2 * hh + 1] * inv;
            *reinterpret_cast<float2*>(
                scores + ((size_t)bh * SEQ + srow) * DK + d) = make_float2(v0, v1);
            __nv_bfloat16 h0, h1, l0, l1;
            split1(v0, h0, l0); split1(v1, h1, l1);
            __nv_bfloat162 hp = __halves2bfloat162(h0, h1);
            __nv_bfloat162 lp = __halves2bfloat162(l0, l1);
            size_t mi = ((size_t)(b * SEQ + srow)) * DMODEL + hhd * DK + d;
            *reinterpret_cast<uint32_t*>(Ao_h + mi) = *reinterpret_cast<uint32_t*>(&hp);
            *reinterpret_cast<uint32_t*>(Ao_l + mi) = *reinterpret_cast<uint32_t*>(&lp);
        }
    }
}

// ---------------------------------------------------------------------------
extern "C" void kernel_launch(void* const* d_in, const int* in_sizes, int n_in,
                              void* d_out, int out_size)
{
    const float* query = (const float*)d_in[0];
    const float* key   = (const float*)d_in[1];
    const float* value = (const float*)d_in[2];
    const float* Wq = (const float*)d_in[3];
    const float* bq = (const float*)d_in[4];
    const float* Wk = (const float*)d_in[5];
    const float* bk = (const float*)d_in[6];
    const float* Wv = (const float*)d_in[7];
    const float* bv = (const float*)d_in[8];
    const float* Wo = (const float*)d_in[9];
    const float* bo = (const float*)d_in[10];

    float* out    = (float*)d_out;
    float* scores = (float*)d_out + QKV_ELEMS;

    __nv_bfloat16 *qh, *ql, *kh, *kl, *vh, *vl, *sh, *sl;
    __nv_bfloat16 *axh, *axl, *wsh, *wsl;
    cudaGetSymbolAddress((void**)&qh, g_Qh);
    cudaGetSymbolAddress((void**)&ql, g_Ql);
    cudaGetSymbolAddress((void**)&kh, g_Kh);
    cudaGetSymbolAddress((void**)&kl, g_Kl);
    cudaGetSymbolAddress((void**)&vh, g_Vh);
    cudaGetSymbolAddress((void**)&vl, g_Vl);
    cudaGetSymbolAddress((void**)&sh, g_Sh);
    cudaGetSymbolAddress((void**)&sl, g_Sl);
    cudaGetSymbolAddress((void**)&axh, g_Axh);
    cudaGetSymbolAddress((void**)&axl, g_Axl);
    cudaGetSymbolAddress((void**)&wsh, g_Wsh);
    cudaGetSymbolAddress((void**)&wsl, g_Wsl);

    const size_t ASTRIDE = (size_t)MROWS * DMODEL;   // 4M elems
    const size_t WSTRIDE = (size_t)DMODEL * DMODEL;  // 1M elems

    cudaFuncSetAttribute(gemm_qkv_kernel,
                         cudaFuncAttributeMaxDynamicSharedMemorySize, GEMM_SMEM);
    cudaFuncSetAttribute(gemm_o_kernel,
                         cudaFuncAttributeMaxDynamicSharedMemorySize, GEMM_SMEM);
    cudaFuncSetAttribute(attn_mma_kernel,
                         cudaFuncAttributeMaxDynamicSharedMemorySize, ATT_SMEM);

    const int nA4 = MROWS * DMODEL / 4;    // 1,048,576
    const int nW4 = DMODEL * DMODEL / 4;   // 262,144

    // 1) split q/k/v inputs (one launch)
    {
        SplitP p{};
        p.src[0] = query; p.src[1] = key; p.src[2] = value;
        for (int z = 0; z < 3; z++) {
            p.hi[z] = axh + z * ASTRIDE;
            p.lo[z] = axl + z * ASTRIDE;
        }
        dim3 grid(nA4 / 256, 3);
        split_many_kernel<<<grid, 256>>>(p, nA4);
    }
    // 2) split all 4 weight matrices (one launch)
    {
        SplitP p{};
        p.src[0] = Wq; p.src[1] = Wk; p.src[2] = Wv; p.src[3] = Wo;
        for (int z = 0; z < 4; z++) {
            p.hi[z] = wsh + z * WSTRIDE;
            p.lo[z] = wsl + z * WSTRIDE;
        }
        dim3 grid(nW4 / 256, 4);
        split_many_kernel<<<grid, 256>>>(p, nW4);
    }
    // 3) Q/K/V projections in one launch (grid.z = 3)
    {
        GemmZP p{};
        const float* biases[3] = {bq, bk, bv};
        __nv_bfloat16* chs[3] = {qh, kh, vh};
        __nv_bfloat16* cls[3] = {ql, kl, vl};
        for (int z = 0; z < 3; z++) {
            p.Ah[z] = axh + z * ASTRIDE;
            p.Al[z] = axl + z * ASTRIDE;
            p.Wh[z] = wsh + z * WSTRIDE;
            p.Wl[z] = wsl + z * WSTRIDE;
            p.bias[z] = biases[z];
            p.Ch[z] = chs[z];
            p.Cl[z] = cls[z];
        }
        p.scale[0] = 0.125f; p.scale[1] = 1.0f; p.scale[2] = 1.0f;
        p.mode[0] = 1; p.mode[1] = 1; p.mode[2] = 2;
        dim3 grid(DMODEL / 128, MROWS / 128, 3);   // (8, 32, 3)
        gemm_qkv_kernel<<<grid, 256, GEMM_SMEM>>>(p);
    }
    // 4) attention: scores fp32 -> d_out, hi/lo split -> g_Sh/g_Sl
    {
        dim3 grid(SEQ / 128, BS * HEADS);          // (16, 32)
        attn_mma_kernel<<<grid, 256, ATT_SMEM>>>(scores, sh, sl);
    }
    // 5) output projection
    {
        dim3 grid(DMODEL / 128, MROWS / 128);      // (8, 32)
        gemm_o_kernel<<<grid, 256, GEMM_SMEM>>>(sh, sl, wsh + 3 * WSTRIDE,
                                                wsl + 3 * WSTRIDE, bo, out);
    }
}

// round 11
// speedup vs baseline: 1.1358x; 1.1358x over previous
#include <cuda_runtime.h>
#include <cuda_bf16.h>
#include <math.h>
#include <stdint.h>

// Problem constants
#define BS      2
#define SEQ     2048
#define DMODEL  1024
#define HEADS   16
#define DK      64
#define MROWS   (BS * SEQ)                  // 4096
#define QKV_ELEMS (BS * HEADS * SEQ * DK)   // 4,194,304

// ---------------------------------------------------------------------------
// Device scratch (allocation-free rule)
// ---------------------------------------------------------------------------
__device__ __align__(16) __nv_bfloat16 g_Qh[QKV_ELEMS];
__device__ __align__(16) __nv_bfloat16 g_Ql[QKV_ELEMS];
__device__ __align__(16) __nv_bfloat16 g_Kh[QKV_ELEMS];
__device__ __align__(16) __nv_bfloat16 g_Kl[QKV_ELEMS];
__device__ __align__(16) __nv_bfloat16 g_Vh[QKV_ELEMS];   // [bh][d][s] transposed
__device__ __align__(16) __nv_bfloat16 g_Vl[QKV_ELEMS];   // [bh][d][s] transposed
__device__ __align__(16) __nv_bfloat16 g_Axh[3][MROWS * DMODEL];
__device__ __align__(16) __nv_bfloat16 g_Axl[3][MROWS * DMODEL];
__device__ __align__(16) __nv_bfloat16 g_Wsh[4][DMODEL * DMODEL];
__device__ __align__(16) __nv_bfloat16 g_Wsl[4][DMODEL * DMODEL];
__device__ __align__(16) __nv_bfloat16 g_Sh[MROWS * DMODEL];
__device__ __align__(16) __nv_bfloat16 g_Sl[MROWS * DMODEL];

// ---------------------------------------------------------------------------
// Helpers
// ---------------------------------------------------------------------------
__device__ __forceinline__ uint32_t smem_u32(const void* p) {
    uint32_t a;
    asm("{ .reg .u64 t; cvta.to.shared.u64 t, %1; cvt.u32.u64 %0, t; }" : "=r"(a) : "l"(p));
    return a;
}
__device__ __forceinline__ uint32_t lds32(uint32_t addr) {
    uint32_t v;
    asm volatile("ld.shared.b32 %0, [%1];" : "=r"(v) : "r"(addr));
    return v;
}
__device__ __forceinline__ void cp_async16(uint32_t saddr, const void* gaddr) {
    asm volatile("cp.async.cg.shared.global [%0], [%1], 16;" :: "r"(saddr), "l"(gaddr));
}
#define CP_COMMIT() asm volatile("cp.async.commit_group;" ::: "memory")
#define CP_WAIT(n)  asm volatile("cp.async.wait_group %0;" :: "n"(n) : "memory")

__device__ __forceinline__ void mma16816(float* c, const uint32_t* a, const uint32_t* b) {
    asm volatile(
        "mma.sync.aligned.m16n8k16.row.col.f32.bf16.bf16.f32 "
        "{%0,%1,%2,%3}, {%4,%5,%6,%7}, {%8,%9}, {%0,%1,%2,%3};"
        : "+f"(c[0]), "+f"(c[1]), "+f"(c[2]), "+f"(c[3])
        : "r"(a[0]), "r"(a[1]), "r"(a[2]), "r"(a[3]), "r"(b[0]), "r"(b[1]));
}
__device__ __forceinline__ void split1(float v, __nv_bfloat16& h, __nv_bfloat16& l) {
    h = __float2bfloat16(v);
    l = __float2bfloat16(v - __bfloat162float(h));
}

// ---------------------------------------------------------------------------
// Fused fp32 -> bf16 hi/lo split (grid.y selects array)
// ---------------------------------------------------------------------------
struct SplitP {
    const float* src[4];
    __nv_bfloat16* hi[4];
    __nv_bfloat16* lo[4];
};

__global__ __launch_bounds__(256) void split_many_kernel(SplitP p, int n4)
{
    int i = blockIdx.x * blockDim.x + threadIdx.x;
    if (i >= n4) return;
    const int which = blockIdx.y;
    const float* __restrict__ src = p.src[which];
    __nv_bfloat16* __restrict__ hi = p.hi[which];
    __nv_bfloat16* __restrict__ lo = p.lo[which];

    int e = i * 4;
    float4 f = reinterpret_cast<const float4*>(src)[i];
    __nv_bfloat16 h0, h1, h2, h3, l0, l1, l2, l3;
    split1(f.x, h0, l0); split1(f.y, h1, l1);
    split1(f.z, h2, l2); split1(f.w, h3, l3);
    __nv_bfloat162 hp0 = __halves2bfloat162(h0, h1), hp1 = __halves2bfloat162(h2, h3);
    __nv_bfloat162 lp0 = __halves2bfloat162(l0, l1), lp1 = __halves2bfloat162(l2, l3);
    uint2 hv, lv;
    hv.x = *reinterpret_cast<uint32_t*>(&hp0); hv.y = *reinterpret_cast<uint32_t*>(&hp1);
    lv.x = *reinterpret_cast<uint32_t*>(&lp0); lv.y = *reinterpret_cast<uint32_t*>(&lp1);
    *reinterpret_cast<uint2*>(hi + e) = hv;
    *reinterpret_cast<uint2*>(lo + e) = lv;
}

// ---------------------------------------------------------------------------
// Shared GEMM mainloop: acc = Ah·Wh + Ah·Wl + Al·Wh
// Restructured for low register liveness: B frags resident (16 regs),
// A frags streamed per-mt (8 regs).
// ---------------------------------------------------------------------------
#define SA        40
#define TILE_B    (128 * SA * 2)
#define BUF_B     (4 * TILE_B)
#define GEMM_SMEM (2 * BUF_B)            // 81920 bytes

__device__ __forceinline__ void gemm_core(
    const __nv_bfloat16* __restrict__ Ah, const __nv_bfloat16* __restrict__ Al,
    const __nv_bfloat16* __restrict__ Wh, const __nv_bfloat16* __restrict__ Wl,
    uint32_t sb, int m0, int n0, int tid, float acc[4][4][4])
{
    const int lane = tid & 31;
    const int wid  = tid >> 5;
    const int wm   = wid >> 2;
    const int wn   = wid & 3;
    const int g    = lane >> 2;
    const int t4   = lane & 3;
    const int lr0 = tid >> 2;
    const int lc0 = (tid & 3) * 8;

#pragma unroll
    for (int mt = 0; mt < 4; mt++)
#pragma unroll
        for (int nt = 0; nt < 4; nt++)
#pragma unroll
            for (int q = 0; q < 4; q++) acc[mt][nt][q] = 0.f;

    auto load_tile = [&](int buf, int k0) {
        uint32_t base = sb + buf * BUF_B;
#pragma unroll
        for (int it = 0; it < 2; it++) {
            int r = lr0 + it * 64;
            uint32_t soff = (uint32_t)(r * SA + lc0) * 2;
            size_t ga = (size_t)(m0 + r) * DMODEL + k0 + lc0;
            size_t gb = (size_t)(n0 + r) * DMODEL + k0 + lc0;
            cp_async16(base + 0 * TILE_B + soff, Ah + ga);
            cp_async16(base + 1 * TILE_B + soff, Al + ga);
            cp_async16(base + 2 * TILE_B + soff, Wh + gb);
            cp_async16(base + 3 * TILE_B + soff, Wl + gb);
        }
        CP_COMMIT();
    };

    load_tile(0, 0);

    const int NT = DMODEL / 32;
    for (int kt = 0; kt < NT; kt++) {
        const int buf = kt & 1;
        if (kt + 1 < NT) {
            load_tile(buf ^ 1, (kt + 1) * 32);
            CP_WAIT(1);
        } else {
            CP_WAIT(0);
        }
        __syncthreads();

        const uint32_t bA = sb + buf * BUF_B;
        const uint32_t bB = bA + 2 * TILE_B;

#pragma unroll
        for (int s = 0; s < 2; s++) {
            const int kc = s * 16 + t4 * 2;
            // B fragments for all nt (resident, 16 regs)
            uint32_t bh[4][2], bl[4][2];
#pragma unroll
            for (int nt = 0; nt < 4; nt++) {
                int n = wn * 32 + nt * 8 + g;
                uint32_t o = (uint32_t)(n * SA + kc) * 2;
                bh[nt][0] = lds32(bB + o);
                bh[nt][1] = lds32(bB + o + 16);
                bl[nt][0] = lds32(bB + TILE_B + o);
                bl[nt][1] = lds32(bB + TILE_B + o + 16);
            }
            // A fragments streamed per mt (8 regs live)
#pragma unroll
            for (int mt = 0; mt < 4; mt++) {
                int row = wm * 64 + mt * 16 + g;
                uint32_t o00 = (uint32_t)(row * SA + kc) * 2;
                uint32_t o10 = o00 + 8 * SA * 2;
                uint32_t ah[4], al[4];
                ah[0] = lds32(bA + o00);
                ah[1] = lds32(bA + o10);
                ah[2] = lds32(bA + o00 + 16);
                ah[3] = lds32(bA + o10 + 16);
                al[0] = lds32(bA + TILE_B + o00);
                al[1] = lds32(bA + TILE_B + o10);
                al[2] = lds32(bA + TILE_B + o00 + 16);
                al[3] = lds32(bA + TILE_B + o10 + 16);
#pragma unroll
                for (int nt = 0; nt < 4; nt++) {
                    mma16816(acc[mt][nt], ah, bh[nt]);
                    mma16816(acc[mt][nt], ah, bl[nt]);
                    mma16816(acc[mt][nt], al, bh[nt]);
                }
            }
        }
        __syncthreads();
    }
}

// ---------------------------------------------------------------------------
// QKV projection GEMM (grid.z in {0=Q, 1=K, 2=V})
// ---------------------------------------------------------------------------
struct GemmZP {
    const __nv_bfloat16 *Ah[3], *Al[3], *Wh[3], *Wl[3];
    const float* bias[3];
    __nv_bfloat16 *Ch[3], *Cl[3];
    float scale[3];
    int mode[3];
};

__global__ __launch_bounds__(256, 2) void gemm_qkv_kernel(GemmZP p)
{
    extern __shared__ __align__(128) char smem[];
    const uint32_t sb = smem_u32(smem);
    const int z = blockIdx.z;
    const int tid = threadIdx.x;
    const int lane = tid & 31;
    const int wid  = tid >> 5;
    const int wm = wid >> 2, wn = wid & 3;
    const int g = lane >> 2, t4 = lane & 3;
    const int m0 = blockIdx.y * 128;
    const int n0 = blockIdx.x * 128;

    float acc[4][4][4];
    gemm_core(p.Ah[z], p.Al[z], p.Wh[z], p.Wl[z], sb, m0, n0, tid, acc);

    const float* bias = p.bias[z];
    __nv_bfloat16* Ch = p.Ch[z];
    __nv_bfloat16* Cl = p.Cl[z];
    const float scale = p.scale[z];
    const int mode = p.mode[z];

#pragma unroll
    for (int mt = 0; mt < 4; mt++) {
        int row0 = m0 + wm * 64 + mt * 16 + g;
#pragma unroll
        for (int nt = 0; nt < 4; nt++) {
            int col = n0 + wn * 32 + nt * 8 + t4 * 2;
            float2 bv = *reinterpret_cast<const float2*>(bias + col);
            float v[2][2];
            v[0][0] = (acc[mt][nt][0] + bv.x) * scale;
            v[0][1] = (acc[mt][nt][1] + bv.y) * scale;
            v[1][0] = (acc[mt][nt][2] + bv.x) * scale;
            v[1][1] = (acc[mt][nt][3] + bv.y) * scale;
            int h = col >> 6, d = col & 63;
#pragma unroll
            for (int rr = 0; rr < 2; rr++) {
                int row = row0 + rr * 8;
                int b = row >> 11, s = row & 2047;
                int bh = b * HEADS + h;
                __nv_bfloat16 h0, h1, l0, l1;
                split1(v[rr][0], h0, l0);
                split1(v[rr][1], h1, l1);
                if (mode == 1) {
                    size_t off = ((size_t)bh * SEQ + s) * DK + d;
                    __nv_bfloat162 hp = __halves2bfloat162(h0, h1);
                    __nv_bfloat162 lp = __halves2bfloat162(l0, l1);
                    *reinterpret_cast<uint32_t*>(Ch + off) = *reinterpret_cast<uint32_t*>(&hp);
                    *reinterpret_cast<uint32_t*>(Cl + off) = *reinterpret_cast<uint32_t*>(&lp);
                } else {
                    size_t o0 = ((size_t)bh * DK + d) * SEQ + s;
                    size_t o1 = ((size_t)bh * DK + d + 1) * SEQ + s;
                    Ch[o0] = h0; Ch[o1] = h1;
                    Cl[o0] = l0; Cl[o1] = l1;
                }
            }
        }
    }
}

// ---------------------------------------------------------------------------
// Output projection GEMM (fp32 out)
// ---------------------------------------------------------------------------
__global__ __launch_bounds__(256, 2) void gemm_o_kernel(
    const __nv_bfloat16* __restrict__ Ah, const __nv_bfloat16* __restrict__ Al,
    const __nv_bfloat16* __restrict__ Wh, const __nv_bfloat16* __restrict__ Wl,
    const float* __restrict__ bias, float* __restrict__ Cf)
{
    extern __shared__ __align__(128) char smem[];
    const uint32_t sb = smem_u32(smem);
    const int tid = threadIdx.x;
    const int lane = tid & 31;
    const int wid  = tid >> 5;
    const int wm = wid >> 2, wn = wid & 3;
    const int g = lane >> 2, t4 = lane & 3;
    const int m0 = blockIdx.y * 128;
    const int n0 = blockIdx.x * 128;

    float acc[4][4][4];
    gemm_core(Ah, Al, Wh, Wl, sb, m0, n0, tid, acc);

#pragma unroll
    for (int mt = 0; mt < 4; mt++) {
        int row0 = m0 + wm * 64 + mt * 16 + g;
#pragma unroll
        for (int nt = 0; nt < 4; nt++) {
            int col = n0 + wn * 32 + nt * 8 + t4 * 2;
            float2 bv = *reinterpret_cast<const float2*>(bias + col);
            *reinterpret_cast<float2*>(Cf + (size_t)row0 * DMODEL + col) =
                make_float2(acc[mt][nt][0] + bv.x, acc[mt][nt][1] + bv.y);
            *reinterpret_cast<float2*>(Cf + (size_t)(row0 + 8) * DMODEL + col) =
                make_float2(acc[mt][nt][2] + bv.x, acc[mt][nt][3] + bv.y);
        }
    }
}

// ---------------------------------------------------------------------------
// Tensor-core flash attention. Q tiles now live in smem (frees ~32 regs),
// __launch_bounds__(256, 2) for 2 CTAs/SM.
// smem: Qh(18432) | Ql(18432) | 2 x [Kh|Kl|Vh|Vl](36864) = 110592 B
// ---------------------------------------------------------------------------
#define ATT_SA    72
#define ATT_TILE  (64 * ATT_SA * 2)        // 9216 B
#define ATT_BUF   (4 * ATT_TILE)           // 36864 B
#define ATT_QT    (128 * ATT_SA * 2)       // 18432 B
#define ATT_CH0   (2 * ATT_QT)             // 36864: chunk buffers base
#define ATT_SMEM  (ATT_CH0 + 2 * ATT_BUF)  // 110592 B

__global__ __launch_bounds__(256, 2) void attn_mma_kernel(
    float* __restrict__ scores,
    __nv_bfloat16* __restrict__ Ao_h, __nv_bfloat16* __restrict__ Ao_l)
{
    extern __shared__ __align__(128) char asmem[];
    const uint32_t sb = smem_u32(asmem);
    const uint32_t sbQ  = sb;
    const uint32_t sbQl = sb + ATT_QT;

    const int tid  = threadIdx.x;
    const int lane = tid & 31;
    const int wid  = tid >> 5;
    const int g    = lane >> 2;
    const int t4   = lane & 3;

    const int bh = blockIdx.y;
    const int q0 = blockIdx.x * 128;
    const int qrl = wid * 16;              // local Q row base for this warp

    // ---- Q tiles into smem (cp.async) ----
#pragma unroll
    for (int it = 0; it < 4; it++) {
        int idx = tid + it * 256;          // 0..1023
        int row = idx >> 3, c8 = idx & 7;
        uint32_t so = (uint32_t)row * (ATT_SA * 2) + c8 * 16;
        size_t gq = ((size_t)bh * SEQ + q0 + row) * DK + c8 * 8;
        cp_async16(sbQ + so, g_Qh + gq);
        cp_async16(sbQl + so, g_Ql + gq);
    }
    CP_COMMIT();

    float o[8][4];
#pragma unroll
    for (int dt = 0; dt < 8; dt++)
#pragma unroll
        for (int q = 0; q < 4; q++) o[dt][q] = 0.f;
    float mrow[2] = {-INFINITY, -INFINITY};
    float lrow[2] = {0.f, 0.f};

    auto load_chunk = [&](int buf, int kt) {
        uint32_t base = sb + ATT_CH0 + buf * ATT_BUF;
#pragma unroll
        for (int it = 0; it < 2; it++) {
            int idx = tid + it * 256;
            int row = idx >> 3, c8 = idx & 7;
            uint32_t so = (uint32_t)row * (ATT_SA * 2) + c8 * 16;
            size_t gk = ((size_t)bh * SEQ + kt * 64 + row) * DK + c8 * 8;
            cp_async16(base + so, g_Kh + gk);
            cp_async16(base + ATT_TILE + so, g_Kl + gk);
            size_t gv = ((size_t)bh * DK + row) * SEQ + kt * 64 + c8 * 8;
            cp_async16(base + 2 * ATT_TILE + so, g_Vh + gv);
            cp_async16(base + 3 * ATT_TILE + so, g_Vl + gv);
        }
        CP_COMMIT();
    };

    load_chunk(0, 0);

    const int NCH = SEQ / 64;   // 32
    for (int kt = 0; kt < NCH; kt++) {
        const int buf = kt & 1;
        if (kt + 1 < NCH) {
            load_chunk(buf ^ 1, kt + 1);
            CP_WAIT(1);
        } else {
            CP_WAIT(0);
        }
        __syncthreads();

        const uint32_t bK  = sb + ATT_CH0 + buf * ATT_BUF;
        const uint32_t bKl = bK + ATT_TILE;
        const uint32_t bV  = bK + 2 * ATT_TILE;
        const uint32_t bVl = bK + 3 * ATT_TILE;

        // ---- S = Q K^T (3-pass), Q fragments from smem ----
        float s[8][4];
#pragma unroll
        for (int nt = 0; nt < 8; nt++)
#pragma unroll
            for (int q = 0; q < 4; q++) s[nt][q] = 0.f;
#pragma unroll
        for (int kf = 0; kf < 4; kf++) {
            uint32_t qoff = (uint32_t)(qrl + g) * (ATT_SA * 2) + (kf * 8 + t4) * 4;
            uint32_t qh[4], ql[4];
            qh[0] = lds32(sbQ + qoff);
            qh[1] = lds32(sbQ + qoff + 8 * ATT_SA * 2);
            qh[2] = lds32(sbQ + qoff + 16);
            qh[3] = lds32(sbQ + qoff + 8 * ATT_SA * 2 + 16);
            ql[0] = lds32(sbQl + qoff);
            ql[1] = lds32(sbQl + qoff + 8 * ATT_SA * 2);
            ql[2] = lds32(sbQl + qoff + 16);
            ql[3] = lds32(sbQl + qoff + 8 * ATT_SA * 2 + 16);
#pragma unroll
            for (int nt = 0; nt < 8; nt++) {
                uint32_t off = ((uint32_t)(nt * 8 + g) * ATT_SA + kf * 16 + t4 * 2) * 2;
                uint32_t kbh[2] = { lds32(bK + off),  lds32(bK + off + 16) };
                uint32_t kbl[2] = { lds32(bKl + off), lds32(bKl + off + 16) };
                mma16816(s[nt], qh, kbh);
                mma16816(s[nt], qh, kbl);
                mma16816(s[nt], ql, kbh);
            }
        }

        // ---- online softmax ----
#pragma unroll
        for (int hh = 0; hh < 2; hh++) {
            float mx = -INFINITY;
#pragma unroll
            for (int nt = 0; nt < 8; nt++)
                mx = fmaxf(mx, fmaxf(s[nt][2 * hh], s[nt][2 * hh + 1]));
            mx = fmaxf(mx, __shfl_xor_sync(0xffffffffu, mx, 1));
            mx = fmaxf(mx, __shfl_xor_sync(0xffffffffu, mx, 2));
            float mnew = fmaxf(mrow[hh], mx);
            float sc = __expf(mrow[hh] - mnew);
            mrow[hh] = mnew;
            float rs = 0.f;
#pragma unroll
            for (int nt = 0; nt < 8; nt++) {
                s[nt][2 * hh]     = __expf(s[nt][2 * hh] - mnew);
                s[nt][2 * hh + 1] = __expf(s[nt][2 * hh + 1] - mnew);
                rs += s[nt][2 * hh] + s[nt][2 * hh + 1];
            }
            rs += __shfl_xor_sync(0xffffffffu, rs, 1);
            rs += __shfl_xor_sync(0xffffffffu, rs, 2);
            lrow[hh] = lrow[hh] * sc + rs;
#pragma unroll
            for (int dt = 0; dt < 8; dt++) {
                o[dt][2 * hh]     *= sc;
                o[dt][2 * hh + 1] *= sc;
            }
        }

        // ---- pack P into A fragments (hi/lo) ----
        uint32_t ph[4][4], pl[4][4];
#pragma unroll
        for (int kf = 0; kf < 4; kf++) {
#pragma unroll
            for (int half = 0; half < 2; half++) {
                const float* sv = s[2 * kf + half];
                __nv_bfloat16 h0, h1, h2, h3, l0, l1, l2, l3;
                split1(sv[0], h0, l0); split1(sv[1], h1, l1);
                split1(sv[2], h2, l2); split1(sv[3], h3, l3);
                __nv_bfloat162 a, b, c, d;
                a = __halves2bfloat162(h0, h1); b = __halves2bfloat162(h2, h3);
                c = __halves2bfloat162(l0, l1); d = __halves2bfloat162(l2, l3);
                ph[kf][2 * half + 0] = *reinterpret_cast<uint32_t*>(&a);
                ph[kf][2 * half + 1] = *reinterpret_cast<uint32_t*>(&b);
                pl[kf][2 * half + 0] = *reinterpret_cast<uint32_t*>(&c);
                pl[kf][2 * half + 1] = *reinterpret_cast<uint32_t*>(&d);
            }
        }

        // ---- O += P V (3-pass) ----
#pragma unroll
        for (int kf = 0; kf < 4; kf++) {
#pragma unroll
            for (int dt = 0; dt < 8; dt++) {
                uint32_t off = ((uint32_t)(dt * 8 + g) * ATT_SA + kf * 16 + t4 * 2) * 2;
                uint32_t vbh[2] = { lds32(bV + off),  lds32(bV + off + 16) };
                uint32_t vbl[2] = { lds32(bVl + off), lds32(bVl + off + 16) };
                mma16816(o[dt], ph[kf], vbh);
                mma16816(o[dt], ph[kf], vbl);
                mma16816(o[dt], pl[kf], vbh);
            }
        }
        __syncthreads();
    }

    // ---- epilogue ----
    const int b = bh >> 4, hhd = bh & 15;
#pragma unroll
    for (int hh = 0; hh < 2; hh++) {
        float inv = 1.f / lrow[hh];
        int srow = q0 + qrl + g + hh * 8;
#pragma unroll
        for (int dt = 0; dt < 8; dt++) {
            int d = dt * 8 + t4 * 2;
            float v0 = o[dt][2 * hh] * inv;
            float v1 = o[dt][2 * hh + 1] * inv;
            *reinterpret_cast<float2*>(
                scores + ((size_t)bh * SEQ + srow) * DK + d) = make_float2(v0, v1);
            __nv_bfloat16 h0, h1, l0, l1;
            split1(v0, h0, l0); split1(v1, h1, l1);
            __nv_bfloat162 hp = __halves2bfloat162(h0, h1);
            __nv_bfloat162 lp = __halves2bfloat162(l0, l1);
            size_t mi = ((size_t)(b * SEQ + srow)) * DMODEL + hhd * DK + d;
            *reinterpret_cast<uint32_t*>(Ao_h + mi) = *reinterpret_cast<uint32_t*>(&hp);
            *reinterpret_cast<uint32_t*>(Ao_l + mi) = *reinterpret_cast<uint32_t*>(&lp);
        }
    }
}

// ---------------------------------------------------------------------------
extern "C" void kernel_launch(void* const* d_in, const int* in_sizes, int n_in,
                              void* d_out, int out_size)
{
    const float* query = (const float*)d_in[0];
    const float* key   = (const float*)d_in[1];
    const float* value = (const float*)d_in[2];
    const float* Wq = (const float*)d_in[3];
    const float* bq = (const float*)d_in[4];
    const float* Wk = (const float*)d_in[5];
    const float* bk = (const float*)d_in[6];
    const float* Wv = (const float*)d_in[7];
    const float* bv = (const float*)d_in[8];
    const float* Wo = (const float*)d_in[9];
    const float* bo = (const float*)d_in[10];

    float* out    = (float*)d_out;
    float* scores = (float*)d_out + QKV_ELEMS;

    __nv_bfloat16 *qh, *ql, *kh, *kl, *vh, *vl, *sh, *sl;
    __nv_bfloat16 *axh, *axl, *wsh, *wsl;
    cudaGetSymbolAddress((void**)&qh, g_Qh);
    cudaGetSymbolAddress((void**)&ql, g_Ql);
    cudaGetSymbolAddress((void**)&kh, g_Kh);
    cudaGetSymbolAddress((void**)&kl, g_Kl);
    cudaGetSymbolAddress((void**)&vh, g_Vh);
    cudaGetSymbolAddress((void**)&vl, g_Vl);
    cudaGetSymbolAddress((void**)&sh, g_Sh);
    cudaGetSymbolAddress((void**)&sl, g_Sl);
    cudaGetSymbolAddress((void**)&axh, g_Axh);
    cudaGetSymbolAddress((void**)&axl, g_Axl);
    cudaGetSymbolAddress((void**)&wsh, g_Wsh);
    cudaGetSymbolAddress((void**)&wsl, g_Wsl);

    const size_t ASTRIDE = (size_t)MROWS * DMODEL;
    const size_t WSTRIDE = (size_t)DMODEL * DMODEL;

    cudaFuncSetAttribute(gemm_qkv_kernel,
                         cudaFuncAttributeMaxDynamicSharedMemorySize, GEMM_SMEM);
    cudaFuncSetAttribute(gemm_o_kernel,
                         cudaFuncAttributeMaxDynamicSharedMemorySize, GEMM_SMEM);
    cudaFuncSetAttribute(attn_mma_kernel,
                         cudaFuncAttributeMaxDynamicSharedMemorySize, ATT_SMEM);

    const int nA4 = MROWS * DMODEL / 4;
    const int nW4 = DMODEL * DMODEL / 4;

    // 1) split q/k/v inputs
    {
        SplitP p{};
        p.src[0] = query; p.src[1] = key; p.src[2] = value;
        for (int z = 0; z < 3; z++) {
            p.hi[z] = axh + z * ASTRIDE;
            p.lo[z] = axl + z * ASTRIDE;
        }
        dim3 grid(nA4 / 256, 3);
        split_many_kernel<<<grid, 256>>>(p, nA4);
    }
    // 2) split weights
    {
        SplitP p{};
        p.src[0] = Wq; p.src[1] = Wk; p.src[2] = Wv; p.src[3] = Wo;
        for (int z = 0; z < 4; z++) {
            p.hi[z] = wsh + z * WSTRIDE;
            p.lo[z] = wsl + z * WSTRIDE;
        }
        dim3 grid(nW4 / 256, 4);
        split_many_kernel<<<grid, 256>>>(p, nW4);
    }
    // 3) Q/K/V projections
    {
        GemmZP p{};
        const float* biases[3] = {bq, bk, bv};
        __nv_bfloat16* chs[3] = {qh, kh, vh};
        __nv_bfloat16* cls[3] = {ql, kl, vl};
        for (int z = 0; z < 3; z++) {
            p.Ah[z] = axh + z * ASTRIDE;
            p.Al[z] = axl + z * ASTRIDE;
            p.Wh[z] = wsh + z * WSTRIDE;
            p.Wl[z] = wsl + z * WSTRIDE;
            p.bias[z] = biases[z];
            p.Ch[z] = chs[z];
            p.Cl[z] = cls[z];
        }
        p.scale[0] = 0.125f; p.scale[1] = 1.0f; p.scale[2] = 1.0f;
        p.mode[0] = 1; p.mode[1] = 1; p.mode[2] = 2;
        dim3 grid(DMODEL / 128, MROWS / 128, 3);
        gemm_qkv_kernel<<<grid, 256, GEMM_SMEM>>>(p);
    }
    // 4) attention
    {
        dim3 grid(SEQ / 128, BS * HEADS);
        attn_mma_kernel<<<grid, 256, ATT_SMEM>>>(scores, sh, sl);
    }
    // 5) output projection
    {
        dim3 grid(DMODEL / 128, MROWS / 128);
        gemm_o_kernel<<<grid, 256, GEMM_SMEM>>>(sh, sl, wsh + 3 * WSTRIDE,
                                                wsl + 3 * WSTRIDE, bo, out);
    }
}

// round 12
// speedup vs baseline: 1.1489x; 1.0115x over previous
#include <cuda_runtime.h>
#include <cuda_bf16.h>
#include <math.h>
#include <stdint.h>

// Problem constants
#define BS      2
#define SEQ     2048
#define DMODEL  1024
#define HEADS   16
#define DK      64
#define MROWS   (BS * SEQ)                  // 4096
#define QKV_ELEMS (BS * HEADS * SEQ * DK)   // 4,194,304

// ---------------------------------------------------------------------------
// Device scratch (allocation-free rule)
// ---------------------------------------------------------------------------
__device__ __align__(16) __nv_bfloat16 g_Qh[QKV_ELEMS];
__device__ __align__(16) __nv_bfloat16 g_Ql[QKV_ELEMS];
__device__ __align__(16) __nv_bfloat16 g_Kh[QKV_ELEMS];
__device__ __align__(16) __nv_bfloat16 g_Kl[QKV_ELEMS];
__device__ __align__(16) __nv_bfloat16 g_Vh[QKV_ELEMS];   // [bh][d][s] transposed
__device__ __align__(16) __nv_bfloat16 g_Vl[QKV_ELEMS];   // [bh][d][s] transposed
__device__ __align__(16) __nv_bfloat16 g_Axh[3][MROWS * DMODEL];
__device__ __align__(16) __nv_bfloat16 g_Axl[3][MROWS * DMODEL];
__device__ __align__(16) __nv_bfloat16 g_Wsh[4][DMODEL * DMODEL];
__device__ __align__(16) __nv_bfloat16 g_Wsl[4][DMODEL * DMODEL];
__device__ __align__(16) __nv_bfloat16 g_Sh[MROWS * DMODEL];
__device__ __align__(16) __nv_bfloat16 g_Sl[MROWS * DMODEL];

// ---------------------------------------------------------------------------
// Helpers
// ---------------------------------------------------------------------------
__device__ __forceinline__ uint32_t smem_u32(const void* p) {
    uint32_t a;
    asm("{ .reg .u64 t; cvta.to.shared.u64 t, %1; cvt.u32.u64 %0, t; }" : "=r"(a) : "l"(p));
    return a;
}
__device__ __forceinline__ uint32_t lds32(uint32_t addr) {
    uint32_t v;
    asm volatile("ld.shared.b32 %0, [%1];" : "=r"(v) : "r"(addr));
    return v;
}
__device__ __forceinline__ void cp_async16(uint32_t saddr, const void* gaddr) {
    asm volatile("cp.async.cg.shared.global [%0], [%1], 16;" :: "r"(saddr), "l"(gaddr));
}
#define CP_COMMIT() asm volatile("cp.async.commit_group;" ::: "memory")
#define CP_WAIT(n)  asm volatile("cp.async.wait_group %0;" :: "n"(n) : "memory")

__device__ __forceinline__ void mma16816(float* c, const uint32_t* a, const uint32_t* b) {
    asm volatile(
        "mma.sync.aligned.m16n8k16.row.col.f32.bf16.bf16.f32 "
        "{%0,%1,%2,%3}, {%4,%5,%6,%7}, {%8,%9}, {%0,%1,%2,%3};"
        : "+f"(c[0]), "+f"(c[1]), "+f"(c[2]), "+f"(c[3])
        : "r"(a[0]), "r"(a[1]), "r"(a[2]), "r"(a[3]), "r"(b[0]), "r"(b[1]));
}
__device__ __forceinline__ void split1(float v, __nv_bfloat16& h, __nv_bfloat16& l) {
    h = __float2bfloat16(v);
    l = __float2bfloat16(v - __bfloat162float(h));
}

// ---------------------------------------------------------------------------
// Fused fp32 -> bf16 hi/lo split (grid.y selects array)
// ---------------------------------------------------------------------------
struct SplitP {
    const float* src[4];
    __nv_bfloat16* hi[4];
    __nv_bfloat16* lo[4];
};

__global__ __launch_bounds__(256) void split_many_kernel(SplitP p, int n4)
{
    int i = blockIdx.x * blockDim.x + threadIdx.x;
    if (i >= n4) return;
    const int which = blockIdx.y;
    const float* __restrict__ src = p.src[which];
    __nv_bfloat16* __restrict__ hi = p.hi[which];
    __nv_bfloat16* __restrict__ lo = p.lo[which];

    int e = i * 4;
    float4 f = reinterpret_cast<const float4*>(src)[i];
    __nv_bfloat16 h0, h1, h2, h3, l0, l1, l2, l3;
    split1(f.x, h0, l0); split1(f.y, h1, l1);
    split1(f.z, h2, l2); split1(f.w, h3, l3);
    __nv_bfloat162 hp0 = __halves2bfloat162(h0, h1), hp1 = __halves2bfloat162(h2, h3);
    __nv_bfloat162 lp0 = __halves2bfloat162(l0, l1), lp1 = __halves2bfloat162(l2, l3);
    uint2 hv, lv;
    hv.x = *reinterpret_cast<uint32_t*>(&hp0); hv.y = *reinterpret_cast<uint32_t*>(&hp1);
    lv.x = *reinterpret_cast<uint32_t*>(&lp0); lv.y = *reinterpret_cast<uint32_t*>(&lp1);
    *reinterpret_cast<uint2*>(hi + e) = hv;
    *reinterpret_cast<uint2*>(lo + e) = lv;
}

// ---------------------------------------------------------------------------
// Shared GEMM mainloop: acc = Ah·Wh + Ah·Wl + Al·Wh  (unchanged from R11)
// ---------------------------------------------------------------------------
#define SA        40
#define TILE_B    (128 * SA * 2)
#define BUF_B     (4 * TILE_B)
#define GEMM_SMEM (2 * BUF_B)            // 81920 bytes

__device__ __forceinline__ void gemm_core(
    const __nv_bfloat16* __restrict__ Ah, const __nv_bfloat16* __restrict__ Al,
    const __nv_bfloat16* __restrict__ Wh, const __nv_bfloat16* __restrict__ Wl,
    uint32_t sb, int m0, int n0, int tid, float acc[4][4][4])
{
    const int lane = tid & 31;
    const int wid  = tid >> 5;
    const int wm   = wid >> 2;
    const int wn   = wid & 3;
    const int g    = lane >> 2;
    const int t4   = lane & 3;
    const int lr0 = tid >> 2;
    const int lc0 = (tid & 3) * 8;

#pragma unroll
    for (int mt = 0; mt < 4; mt++)
#pragma unroll
        for (int nt = 0; nt < 4; nt++)
#pragma unroll
            for (int q = 0; q < 4; q++) acc[mt][nt][q] = 0.f;

    auto load_tile = [&](int buf, int k0) {
        uint32_t base = sb + buf * BUF_B;
#pragma unroll
        for (int it = 0; it < 2; it++) {
            int r = lr0 + it * 64;
            uint32_t soff = (uint32_t)(r * SA + lc0) * 2;
            size_t ga = (size_t)(m0 + r) * DMODEL + k0 + lc0;
            size_t gb = (size_t)(n0 + r) * DMODEL + k0 + lc0;
            cp_async16(base + 0 * TILE_B + soff, Ah + ga);
            cp_async16(base + 1 * TILE_B + soff, Al + ga);
            cp_async16(base + 2 * TILE_B + soff, Wh + gb);
            cp_async16(base + 3 * TILE_B + soff, Wl + gb);
        }
        CP_COMMIT();
    };

    load_tile(0, 0);

    const int NT = DMODEL / 32;
    for (int kt = 0; kt < NT; kt++) {
        const int buf = kt & 1;
        if (kt + 1 < NT) {
            load_tile(buf ^ 1, (kt + 1) * 32);
            CP_WAIT(1);
        } else {
            CP_WAIT(0);
        }
        __syncthreads();

        const uint32_t bA = sb + buf * BUF_B;
        const uint32_t bB = bA + 2 * TILE_B;

#pragma unroll
        for (int s = 0; s < 2; s++) {
            const int kc = s * 16 + t4 * 2;
            uint32_t bh[4][2], bl[4][2];
#pragma unroll
            for (int nt = 0; nt < 4; nt++) {
                int n = wn * 32 + nt * 8 + g;
                uint32_t o = (uint32_t)(n * SA + kc) * 2;
                bh[nt][0] = lds32(bB + o);
                bh[nt][1] = lds32(bB + o + 16);
                bl[nt][0] = lds32(bB + TILE_B + o);
                bl[nt][1] = lds32(bB + TILE_B + o + 16);
            }
#pragma unroll
            for (int mt = 0; mt < 4; mt++) {
                int row = wm * 64 + mt * 16 + g;
                uint32_t o00 = (uint32_t)(row * SA + kc) * 2;
                uint32_t o10 = o00 + 8 * SA * 2;
                uint32_t ah[4], al[4];
                ah[0] = lds32(bA + o00);
                ah[1] = lds32(bA + o10);
                ah[2] = lds32(bA + o00 + 16);
                ah[3] = lds32(bA + o10 + 16);
                al[0] = lds32(bA + TILE_B + o00);
                al[1] = lds32(bA + TILE_B + o10);
                al[2] = lds32(bA + TILE_B + o00 + 16);
                al[3] = lds32(bA + TILE_B + o10 + 16);
#pragma unroll
                for (int nt = 0; nt < 4; nt++) {
                    mma16816(acc[mt][nt], ah, bh[nt]);
                    mma16816(acc[mt][nt], ah, bl[nt]);
                    mma16816(acc[mt][nt], al, bh[nt]);
                }
            }
        }
        __syncthreads();
    }
}

// ---------------------------------------------------------------------------
// QKV projection GEMM (grid.z in {0=Q, 1=K, 2=V})
// ---------------------------------------------------------------------------
struct GemmZP {
    const __nv_bfloat16 *Ah[3], *Al[3], *Wh[3], *Wl[3];
    const float* bias[3];
    __nv_bfloat16 *Ch[3], *Cl[3];
    float scale[3];
    int mode[3];
};

__global__ __launch_bounds__(256, 2) void gemm_qkv_kernel(GemmZP p)
{
    extern __shared__ __align__(128) char smem[];
    const uint32_t sb = smem_u32(smem);
    const int z = blockIdx.z;
    const int tid = threadIdx.x;
    const int lane = tid & 31;
    const int wid  = tid >> 5;
    const int wm = wid >> 2, wn = wid & 3;
    const int g = lane >> 2, t4 = lane & 3;
    const int m0 = blockIdx.y * 128;
    const int n0 = blockIdx.x * 128;

    float acc[4][4][4];
    gemm_core(p.Ah[z], p.Al[z], p.Wh[z], p.Wl[z], sb, m0, n0, tid, acc);

    const float* bias = p.bias[z];
    __nv_bfloat16* Ch = p.Ch[z];
    __nv_bfloat16* Cl = p.Cl[z];
    const float scale = p.scale[z];
    const int mode = p.mode[z];

#pragma unroll
    for (int mt = 0; mt < 4; mt++) {
        int row0 = m0 + wm * 64 + mt * 16 + g;
#pragma unroll
        for (int nt = 0; nt < 4; nt++) {
            int col = n0 + wn * 32 + nt * 8 + t4 * 2;
            float2 bv = *reinterpret_cast<const float2*>(bias + col);
            float v[2][2];
            v[0][0] = (acc[mt][nt][0] + bv.x) * scale;
            v[0][1] = (acc[mt][nt][1] + bv.y) * scale;
            v[1][0] = (acc[mt][nt][2] + bv.x) * scale;
            v[1][1] = (acc[mt][nt][3] + bv.y) * scale;
            int h = col >> 6, d = col & 63;
#pragma unroll
            for (int rr = 0; rr < 2; rr++) {
                int row = row0 + rr * 8;
                int b = row >> 11, s = row & 2047;
                int bh = b * HEADS + h;
                __nv_bfloat16 h0, h1, l0, l1;
                split1(v[rr][0], h0, l0);
                split1(v[rr][1], h1, l1);
                if (mode == 1) {
                    size_t off = ((size_t)bh * SEQ + s) * DK + d;
                    __nv_bfloat162 hp = __halves2bfloat162(h0, h1);
                    __nv_bfloat162 lp = __halves2bfloat162(l0, l1);
                    *reinterpret_cast<uint32_t*>(Ch + off) = *reinterpret_cast<uint32_t*>(&hp);
                    *reinterpret_cast<uint32_t*>(Cl + off) = *reinterpret_cast<uint32_t*>(&lp);
                } else {
                    size_t o0 = ((size_t)bh * DK + d) * SEQ + s;
                    size_t o1 = ((size_t)bh * DK + d + 1) * SEQ + s;
                    Ch[o0] = h0; Ch[o1] = h1;
                    Cl[o0] = l0; Cl[o1] = l1;
                }
            }
        }
    }
}

// ---------------------------------------------------------------------------
// Output projection GEMM (fp32 out)
// ---------------------------------------------------------------------------
__global__ __launch_bounds__(256, 2) void gemm_o_kernel(
    const __nv_bfloat16* __restrict__ Ah, const __nv_bfloat16* __restrict__ Al,
    const __nv_bfloat16* __restrict__ Wh, const __nv_bfloat16* __restrict__ Wl,
    const float* __restrict__ bias, float* __restrict__ Cf)
{
    extern __shared__ __align__(128) char smem[];
    const uint32_t sb = smem_u32(smem);
    const int tid = threadIdx.x;
    const int lane = tid & 31;
    const int wid  = tid >> 5;
    const int wm = wid >> 2, wn = wid & 3;
    const int g = lane >> 2, t4 = lane & 3;
    const int m0 = blockIdx.y * 128;
    const int n0 = blockIdx.x * 128;

    float acc[4][4][4];
    gemm_core(Ah, Al, Wh, Wl, sb, m0, n0, tid, acc);

#pragma unroll
    for (int mt = 0; mt < 4; mt++) {
        int row0 = m0 + wm * 64 + mt * 16 + g;
#pragma unroll
        for (int nt = 0; nt < 4; nt++) {
            int col = n0 + wn * 32 + nt * 8 + t4 * 2;
            float2 bv = *reinterpret_cast<const float2*>(bias + col);
            *reinterpret_cast<float2*>(Cf + (size_t)row0 * DMODEL + col) =
                make_float2(acc[mt][nt][0] + bv.x, acc[mt][nt][1] + bv.y);
            *reinterpret_cast<float2*>(Cf + (size_t)(row0 + 8) * DMODEL + col) =
                make_float2(acc[mt][nt][2] + bv.x, acc[mt][nt][3] + bv.y);
        }
    }
}

// ---------------------------------------------------------------------------
// Tensor-core flash attention, warp tile 32 Q rows (2 m-tiles/warp):
// CTA = 128 threads (4 warps) = 128 Q rows; K/V fragments loaded once per
// (kf, nt/dt) and reused by both m-tiles -> ~1.8x less smem crossbar traffic
// per MMA. smem layout unchanged: Qh|Ql|2x[Kh|Kl|Vh|Vl] = 110592 B, 2 CTA/SM.
// ---------------------------------------------------------------------------
#define ATT_SA    72
#define ATT_TILE  (64 * ATT_SA * 2)        // 9216 B
#define ATT_BUF   (4 * ATT_TILE)           // 36864 B
#define ATT_QT    (128 * ATT_SA * 2)       // 18432 B
#define ATT_CH0   (2 * ATT_QT)             // 36864
#define ATT_SMEM  (ATT_CH0 + 2 * ATT_BUF)  // 110592 B

__global__ __launch_bounds__(128, 2) void attn_mma_kernel(
    float* __restrict__ scores,
    __nv_bfloat16* __restrict__ Ao_h, __nv_bfloat16* __restrict__ Ao_l)
{
    extern __shared__ __align__(128) char asmem[];
    const uint32_t sb = smem_u32(asmem);
    const uint32_t sbQ  = sb;
    const uint32_t sbQl = sb + ATT_QT;

    const int tid  = threadIdx.x;
    const int lane = tid & 31;
    const int wid  = tid >> 5;            // 0..3
    const int g    = lane >> 2;
    const int t4   = lane & 3;

    const int bh = blockIdx.y;
    const int q0 = blockIdx.x * 128;
    const int qrl = wid * 32;             // warp's local Q row base (2 m-tiles)

    // ---- Q tiles into smem (cp.async): 128 rows x 64 bf16, hi+lo ----
#pragma unroll
    for (int it = 0; it < 8; it++) {
        int idx = tid + it * 128;          // 0..1023
        int row = idx >> 3, c8 = idx & 7;
        uint32_t so = (uint32_t)row * (ATT_SA * 2) + c8 * 16;
        size_t gq = ((size_t)bh * SEQ + q0 + row) * DK + c8 * 8;
        cp_async16(sbQ + so, g_Qh + gq);
        cp_async16(sbQl + so, g_Ql + gq);
    }
    CP_COMMIT();

    float o[2][8][4];
#pragma unroll
    for (int mt = 0; mt < 2; mt++)
#pragma unroll
        for (int dt = 0; dt < 8; dt++)
#pragma unroll
            for (int q = 0; q < 4; q++) o[mt][dt][q] = 0.f;
    float mrow[2][2] = {{-INFINITY, -INFINITY}, {-INFINITY, -INFINITY}};
    float lrow[2][2] = {{0.f, 0.f}, {0.f, 0.f}};

    auto load_chunk = [&](int buf, int kt) {
        uint32_t base = sb + ATT_CH0 + buf * ATT_BUF;
#pragma unroll
        for (int it = 0; it < 4; it++) {
            int idx = tid + it * 128;      // 0..511
            int row = idx >> 3, c8 = idx & 7;
            uint32_t so = (uint32_t)row * (ATT_SA * 2) + c8 * 16;
            size_t gk = ((size_t)bh * SEQ + kt * 64 + row) * DK + c8 * 8;
            cp_async16(base + so, g_Kh + gk);
            cp_async16(base + ATT_TILE + so, g_Kl + gk);
            size_t gv = ((size_t)bh * DK + row) * SEQ + kt * 64 + c8 * 8;
            cp_async16(base + 2 * ATT_TILE + so, g_Vh + gv);
            cp_async16(base + 3 * ATT_TILE + so, g_Vl + gv);
        }
        CP_COMMIT();
    };

    load_chunk(0, 0);

    const int NCH = SEQ / 64;   // 32
    for (int kt = 0; kt < NCH; kt++) {
        const int buf = kt & 1;
        if (kt + 1 < NCH) {
            load_chunk(buf ^ 1, kt + 1);
            CP_WAIT(1);
        } else {
            CP_WAIT(0);
        }
        __syncthreads();

        const uint32_t bK  = sb + ATT_CH0 + buf * ATT_BUF;
        const uint32_t bKl = bK + ATT_TILE;
        const uint32_t bV  = bK + 2 * ATT_TILE;
        const uint32_t bVl = bK + 3 * ATT_TILE;

        // ---- S = Q K^T (3-pass), K frags shared across both m-tiles ----
        float s[2][8][4];
#pragma unroll
        for (int mt = 0; mt < 2; mt++)
#pragma unroll
            for (int nt = 0; nt < 8; nt++)
#pragma unroll
                for (int q = 0; q < 4; q++) s[mt][nt][q] = 0.f;
#pragma unroll
        for (int kf = 0; kf < 4; kf++) {
            uint32_t qc = (uint32_t)(kf * 8 + t4) * 4;
            uint32_t q0off = (uint32_t)(qrl + g) * (ATT_SA * 2) + qc;
            uint32_t q1off = (uint32_t)(qrl + 16 + g) * (ATT_SA * 2) + qc;
            uint32_t qh0[4], ql0[4], qh1[4], ql1[4];
            qh0[0] = lds32(sbQ + q0off);
            qh0[1] = lds32(sbQ + q0off + 8 * ATT_SA * 2);
            qh0[2] = lds32(sbQ + q0off + 16);
            qh0[3] = lds32(sbQ + q0off + 8 * ATT_SA * 2 + 16);
            ql0[0] = lds32(sbQl + q0off);
            ql0[1] = lds32(sbQl + q0off + 8 * ATT_SA * 2);
            ql0[2] = lds32(sbQl + q0off + 16);
            ql0[3] = lds32(sbQl + q0off + 8 * ATT_SA * 2 + 16);
            qh1[0] = lds32(sbQ + q1off);
            qh1[1] = lds32(sbQ + q1off + 8 * ATT_SA * 2);
            qh1[2] = lds32(sbQ + q1off + 16);
            qh1[3] = lds32(sbQ + q1off + 8 * ATT_SA * 2 + 16);
            ql1[0] = lds32(sbQl + q1off);
            ql1[1] = lds32(sbQl + q1off + 8 * ATT_SA * 2);
            ql1[2] = lds32(sbQl + q1off + 16);
            ql1[3] = lds32(sbQl + q1off + 8 * ATT_SA * 2 + 16);
#pragma unroll
            for (int nt = 0; nt < 8; nt++) {
                uint32_t off = ((uint32_t)(nt * 8 + g) * ATT_SA + kf * 16 + t4 * 2) * 2;
                uint32_t kbh[2] = { lds32(bK + off),  lds32(bK + off + 16) };
                uint32_t kbl[2] = { lds32(bKl + off), lds32(bKl + off + 16) };
                mma16816(s[0][nt], qh0, kbh);
                mma16816(s[0][nt], qh0, kbl);
                mma16816(s[0][nt], ql0, kbh);
                mma16816(s[1][nt], qh1, kbh);
                mma16816(s[1][nt], qh1, kbl);
                mma16816(s[1][nt], ql1, kbh);
            }
        }

        // ---- online softmax (per m-tile, rows g and g+8) ----
#pragma unroll
        for (int mt = 0; mt < 2; mt++) {
#pragma unroll
            for (int hh = 0; hh < 2; hh++) {
                float mx = -INFINITY;
#pragma unroll
                for (int nt = 0; nt < 8; nt++)
                    mx = fmaxf(mx, fmaxf(s[mt][nt][2 * hh], s[mt][nt][2 * hh + 1]));
                mx = fmaxf(mx, __shfl_xor_sync(0xffffffffu, mx, 1));
                mx = fmaxf(mx, __shfl_xor_sync(0xffffffffu, mx, 2));
                float mnew = fmaxf(mrow[mt][hh], mx);
                float sc = __expf(mrow[mt][hh] - mnew);
                mrow[mt][hh] = mnew;
                float rs = 0.f;
#pragma unroll
                for (int nt = 0; nt < 8; nt++) {
                    s[mt][nt][2 * hh]     = __expf(s[mt][nt][2 * hh] - mnew);
                    s[mt][nt][2 * hh + 1] = __expf(s[mt][nt][2 * hh + 1] - mnew);
                    rs += s[mt][nt][2 * hh] + s[mt][nt][2 * hh + 1];
                }
                rs += __shfl_xor_sync(0xffffffffu, rs, 1);
                rs += __shfl_xor_sync(0xffffffffu, rs, 2);
                lrow[mt][hh] = lrow[mt][hh] * sc + rs;
#pragma unroll
                for (int dt = 0; dt < 8; dt++) {
                    o[mt][dt][2 * hh]     *= sc;
                    o[mt][dt][2 * hh + 1] *= sc;
                }
            }
        }

        // ---- pack P into A fragments (hi/lo), s dies here ----
        uint32_t ph[2][4][4], pl[2][4][4];
#pragma unroll
        for (int mt = 0; mt < 2; mt++) {
#pragma unroll
            for (int kf = 0; kf < 4; kf++) {
#pragma unroll
                for (int half = 0; half < 2; half++) {
                    const float* sv = s[mt][2 * kf + half];
                    __nv_bfloat16 h0, h1, h2, h3, l0, l1, l2, l3;
                    split1(sv[0], h0, l0); split1(sv[1], h1, l1);
                    split1(sv[2], h2, l2); split1(sv[3], h3, l3);
                    __nv_bfloat162 a, b, c, d;
                    a = __halves2bfloat162(h0, h1); b = __halves2bfloat162(h2, h3);
                    c = __halves2bfloat162(l0, l1); d = __halves2bfloat162(l2, l3);
                    ph[mt][kf][2 * half + 0] = *reinterpret_cast<uint32_t*>(&a);
                    ph[mt][kf][2 * half + 1] = *reinterpret_cast<uint32_t*>(&b);
                    pl[mt][kf][2 * half + 0] = *reinterpret_cast<uint32_t*>(&c);
                    pl[mt][kf][2 * half + 1] = *reinterpret_cast<uint32_t*>(&d);
                }
            }
        }

        // ---- O += P V (3-pass), V frags shared across both m-tiles ----
#pragma unroll
        for (int kf = 0; kf < 4; kf++) {
#pragma unroll
            for (int dt = 0; dt < 8; dt++) {
                uint32_t off = ((uint32_t)(dt * 8 + g) * ATT_SA + kf * 16 + t4 * 2) * 2;
                uint32_t vbh[2] = { lds32(bV + off),  lds32(bV + off + 16) };
                uint32_t vbl[2] = { lds32(bVl + off), lds32(bVl + off + 16) };
                mma16816(o[0][dt], ph[0][kf], vbh);
                mma16816(o[0][dt], ph[0][kf], vbl);
                mma16816(o[0][dt], pl[0][kf], vbh);
                mma16816(o[1][dt], ph[1][kf], vbh);
                mma16816(o[1][dt], ph[1][kf], vbl);
                mma16816(o[1][dt], pl[1][kf], vbh);
            }
        }
        __syncthreads();
    }

    // ---- epilogue ----
    const int b = bh >> 4, hhd = bh & 15;
#pragma unroll
    for (int mt = 0; mt < 2; mt++) {
#pragma unroll
        for (int hh = 0; hh < 2; hh++) {
            float inv = 1.f / lrow[mt][hh];
            int srow = q0 + qrl + mt * 16 + g + hh * 8;
#pragma unroll
            for (int dt = 0; dt < 8; dt++) {
                int d = dt * 8 + t4 * 2;
                float v0 = o[mt][dt][2 * hh] * inv;
                float v1 = o[mt][dt][2 * hh + 1] * inv;
                *reinterpret_cast<float2*>(
                    scores + ((size_t)bh * SEQ + srow) * DK + d) = make_float2(v0, v1);
                __nv_bfloat16 h0, h1, l0, l1;
                split1(v0, h0, l0); split1(v1, h1, l1);
                __nv_bfloat162 hp = __halves2bfloat162(h0, h1);
                __nv_bfloat162 lp = __halves2bfloat162(l0, l1);
                size_t mi = ((size_t)(b * SEQ + srow)) * DMODEL + hhd * DK + d;
                *reinterpret_cast<uint32_t*>(Ao_h + mi) = *reinterpret_cast<uint32_t*>(&hp);
                *reinterpret_cast<uint32_t*>(Ao_l + mi) = *reinterpret_cast<uint32_t*>(&lp);
            }
        }
    }
}

// ---------------------------------------------------------------------------
extern "C" void kernel_launch(void* const* d_in, const int* in_sizes, int n_in,
                              void* d_out, int out_size)
{
    const float* query = (const float*)d_in[0];
    const float* key   = (const float*)d_in[1];
    const float* value = (const float*)d_in[2];
    const float* Wq = (const float*)d_in[3];
    const float* bq = (const float*)d_in[4];
    const float* Wk = (const float*)d_in[5];
    const float* bk = (const float*)d_in[6];
    const float* Wv = (const float*)d_in[7];
    const float* bv = (const float*)d_in[8];
    const float* Wo = (const float*)d_in[9];
    const float* bo = (const float*)d_in[10];

    float* out    = (float*)d_out;
    float* scores = (float*)d_out + QKV_ELEMS;

    __nv_bfloat16 *qh, *ql, *kh, *kl, *vh, *vl, *sh, *sl;
    __nv_bfloat16 *axh, *axl, *wsh, *wsl;
    cudaGetSymbolAddress((void**)&qh, g_Qh);
    cudaGetSymbolAddress((void**)&ql, g_Ql);
    cudaGetSymbolAddress((void**)&kh, g_Kh);
    cudaGetSymbolAddress((void**)&kl, g_Kl);
    cudaGetSymbolAddress((void**)&vh, g_Vh);
    cudaGetSymbolAddress((void**)&vl, g_Vl);
    cudaGetSymbolAddress((void**)&sh, g_Sh);
    cudaGetSymbolAddress((void**)&sl, g_Sl);
    cudaGetSymbolAddress((void**)&axh, g_Axh);
    cudaGetSymbolAddress((void**)&axl, g_Axl);
    cudaGetSymbolAddress((void**)&wsh, g_Wsh);
    cudaGetSymbolAddress((void**)&wsl, g_Wsl);

    const size_t ASTRIDE = (size_t)MROWS * DMODEL;
    const size_t WSTRIDE = (size_t)DMODEL * DMODEL;

    cudaFuncSetAttribute(gemm_qkv_kernel,
                         cudaFuncAttributeMaxDynamicSharedMemorySize, GEMM_SMEM);
    cudaFuncSetAttribute(gemm_o_kernel,
                         cudaFuncAttributeMaxDynamicSharedMemorySize, GEMM_SMEM);
    cudaFuncSetAttribute(attn_mma_kernel,
                         cudaFuncAttributeMaxDynamicSharedMemorySize, ATT_SMEM);

    const int nA4 = MROWS * DMODEL / 4;
    const int nW4 = DMODEL * DMODEL / 4;

    // 1) split q/k/v inputs
    {
        SplitP p{};
        p.src[0] = query; p.src[1] = key; p.src[2] = value;
        for (int z = 0; z < 3; z++) {
            p.hi[z] = axh + z * ASTRIDE;
            p.lo[z] = axl + z * ASTRIDE;
        }
        dim3 grid(nA4 / 256, 3);
        split_many_kernel<<<grid, 256>>>(p, nA4);
    }
    // 2) split weights
    {
        SplitP p{};
        p.src[0] = Wq; p.src[1] = Wk; p.src[2] = Wv; p.src[3] = Wo;
        for (int z = 0; z < 4; z++) {
            p.hi[z] = wsh + z * WSTRIDE;
            p.lo[z] = wsl + z * WSTRIDE;
        }
        dim3 grid(nW4 / 256, 4);
        split_many_kernel<<<grid, 256>>>(p, nW4);
    }
    // 3) Q/K/V projections
    {
        GemmZP p{};
        const float* biases[3] = {bq, bk, bv};
        __nv_bfloat16* chs[3] = {qh, kh, vh};
        __nv_bfloat16* cls[3] = {ql, kl, vl};
        for (int z = 0; z < 3; z++) {
            p.Ah[z] = axh + z * ASTRIDE;
            p.Al[z] = axl + z * ASTRIDE;
            p.Wh[z] = wsh + z * WSTRIDE;
            p.Wl[z] = wsl + z * WSTRIDE;
            p.bias[z] = biases[z];
            p.Ch[z] = chs[z];
            p.Cl[z] = cls[z];
        }
        p.scale[0] = 0.125f; p.scale[1] = 1.0f; p.scale[2] = 1.0f;
        p.mode[0] = 1; p.mode[1] = 1; p.mode[2] = 2;
        dim3 grid(DMODEL / 128, MROWS / 128, 3);
        gemm_qkv_kernel<<<grid, 256, GEMM_SMEM>>>(p);
    }
    // 4) attention (128-thread CTAs, 32 rows/warp)
    {
        dim3 grid(SEQ / 128, BS * HEADS);
        attn_mma_kernel<<<grid, 128, ATT_SMEM>>>(scores, sh, sl);
    }
    // 5) output projection
    {
        dim3 grid(DMODEL / 128, MROWS / 128);
        gemm_o_kernel<<<grid, 256, GEMM_SMEM>>>(sh, sl, wsh + 3 * WSTRIDE,
                                                wsl + 3 * WSTRIDE, bo, out);
    }
}

// round 14
// speedup vs baseline: 1.2300x; 1.0706x over previous
#include <cuda_runtime.h>
#include <cuda_bf16.h>
#include <math.h>
#include <stdint.h>

// Problem constants
#define BS      2
#define SEQ     2048
#define DMODEL  1024
#define HEADS   16
#define DK      64
#define MROWS   (BS * SEQ)                  // 4096
#define QKV_ELEMS (BS * HEADS * SEQ * DK)   // 4,194,304

// ---------------------------------------------------------------------------
// Device scratch (allocation-free rule)
// NOTE: g_Axh/g_Axl/g_Wsh/g_Wsl/g_Sh/g_Sl hold PERMUTED k-blocks:
//   within each 16-elem k block, position order is
//   [k0,k1,k8,k9, k2,k3,k10,k11, k4,k5,k12,k13, k6,k7,k14,k15]
//   so an m16n8k16 fragment half (k{2t4,2t4+1},k{2t4+8,2t4+9}) is 8 contiguous
//   bytes at byte offset t4*8 -> LDS.64 fragment loads in the GEMM.
// g_Q*/g_K*/g_V* stay in NORMAL layout (consumed by the attention kernel).
// ---------------------------------------------------------------------------
__device__ __align__(16) __nv_bfloat16 g_Qh[QKV_ELEMS];
__device__ __align__(16) __nv_bfloat16 g_Ql[QKV_ELEMS];
__device__ __align__(16) __nv_bfloat16 g_Kh[QKV_ELEMS];
__device__ __align__(16) __nv_bfloat16 g_Kl[QKV_ELEMS];
__device__ __align__(16) __nv_bfloat16 g_Vh[QKV_ELEMS];   // [bh][d][s] transposed
__device__ __align__(16) __nv_bfloat16 g_Vl[QKV_ELEMS];   // [bh][d][s] transposed
__device__ __align__(16) __nv_bfloat16 g_Axh[3][MROWS * DMODEL];
__device__ __align__(16) __nv_bfloat16 g_Axl[3][MROWS * DMODEL];
__device__ __align__(16) __nv_bfloat16 g_Wsh[4][DMODEL * DMODEL];
__device__ __align__(16) __nv_bfloat16 g_Wsl[4][DMODEL * DMODEL];
__device__ __align__(16) __nv_bfloat16 g_Sh[MROWS * DMODEL];
__device__ __align__(16) __nv_bfloat16 g_Sl[MROWS * DMODEL];

// ---------------------------------------------------------------------------
// Helpers
// ---------------------------------------------------------------------------
__device__ __forceinline__ uint32_t smem_u32(const void* p) {
    uint32_t a;
    asm("{ .reg .u64 t; cvta.to.shared.u64 t, %1; cvt.u32.u64 %0, t; }" : "=r"(a) : "l"(p));
    return a;
}
__device__ __forceinline__ uint32_t lds32(uint32_t addr) {
    uint32_t v;
    asm volatile("ld.shared.b32 %0, [%1];" : "=r"(v) : "r"(addr));
    return v;
}
__device__ __forceinline__ uint2 lds64(uint32_t addr) {
    uint2 v;
    asm volatile("ld.shared.v2.b32 {%0,%1}, [%2];" : "=r"(v.x), "=r"(v.y) : "r"(addr));
    return v;
}
__device__ __forceinline__ void cp_async16(uint32_t saddr, const void* gaddr) {
    asm volatile("cp.async.cg.shared.global [%0], [%1], 16;" :: "r"(saddr), "l"(gaddr));
}
#define CP_COMMIT() asm volatile("cp.async.commit_group;" ::: "memory")
#define CP_WAIT(n)  asm volatile("cp.async.wait_group %0;" :: "n"(n) : "memory")

__device__ __forceinline__ void mma16816(float* c, const uint32_t* a, const uint32_t* b) {
    asm volatile(
        "mma.sync.aligned.m16n8k16.row.col.f32.bf16.bf16.f32 "
        "{%0,%1,%2,%3}, {%4,%5,%6,%7}, {%8,%9}, {%0,%1,%2,%3};"
        : "+f"(c[0]), "+f"(c[1]), "+f"(c[2]), "+f"(c[3])
        : "r"(a[0]), "r"(a[1]), "r"(a[2]), "r"(a[3]), "r"(b[0]), "r"(b[1]));
}
__device__ __forceinline__ void split1(float v, __nv_bfloat16& h, __nv_bfloat16& l) {
    h = __float2bfloat16(v);
    l = __float2bfloat16(v - __bfloat162float(h));
}

// no-op: shifts ncu's captured launch slot so #4 = gemm_qkv_kernel
__global__ void warmup_noop() {}

// ---------------------------------------------------------------------------
// Fused fp32 -> bf16 hi/lo split with PERMUTED 16-elem k-blocks.
// One thread per 16-elem block: reads 4 float4, writes 2 uint4 hi + 2 uint4 lo.
// Pair j holds (k2j, k2j+1); output pair order = [0,4,1,5,2,6,3,7].
// ---------------------------------------------------------------------------
struct SplitP {
    const float* src[4];
    __nv_bfloat16* hi[4];
    __nv_bfloat16* lo[4];
};

__global__ __launch_bounds__(256) void split_many_kernel(SplitP p, int n16)
{
    int i = blockIdx.x * blockDim.x + threadIdx.x;
    if (i >= n16) return;
    const int which = blockIdx.y;
    const float4* src = reinterpret_cast<const float4*>(p.src[which]) + (size_t)i * 4;

    float f[16];
#pragma unroll
    for (int q = 0; q < 4; q++) {
        float4 v = src[q];
        f[4 * q + 0] = v.x; f[4 * q + 1] = v.y;
        f[4 * q + 2] = v.z; f[4 * q + 3] = v.w;
    }
    uint32_t hp[8], lp[8];
#pragma unroll
    for (int j = 0; j < 8; j++) {
        __nv_bfloat16 h0, h1, l0, l1;
        split1(f[2 * j],     h0, l0);
        split1(f[2 * j + 1], h1, l1);
        __nv_bfloat162 hh = __halves2bfloat162(h0, h1);
        __nv_bfloat162 ll = __halves2bfloat162(l0, l1);
        hp[j] = *reinterpret_cast<uint32_t*>(&hh);
        lp[j] = *reinterpret_cast<uint32_t*>(&ll);
    }
    uint4* ho = reinterpret_cast<uint4*>(p.hi[which] + (size_t)i * 16);
    uint4* lo = reinterpret_cast<uint4*>(p.lo[which] + (size_t)i * 16);
    ho[0] = make_uint4(hp[0], hp[4], hp[1], hp[5]);
    ho[1] = make_uint4(hp[2], hp[6], hp[3], hp[7]);
    lo[0] = make_uint4(lp[0], lp[4], lp[1], lp[5]);
    lo[1] = make_uint4(lp[2], lp[6], lp[3], lp[7]);
}

// ---------------------------------------------------------------------------
// Shared GEMM mainloop: acc = Ah·Wh + Ah·Wl + Al·Wh
// Inputs in permuted-block layout; fragment loads are LDS.64.
// SA=48 elems (96 B rows, 24-word stride): the 8-word LDS.64 spans of rows
// g..g+3 map to word sets {0..7},{24..31},{16..23},{8..15} -> conflict-free.
// ---------------------------------------------------------------------------
#define SA        48
#define TILE_B    (128 * SA * 2)         // 12288 B
#define BUF_B     (4 * TILE_B)           // 49152 B (Ah|Al|Wh|Wl)
#define GEMM_SMEM (2 * BUF_B)            // 98304 B, 2 CTAs/SM

__device__ __forceinline__ void gemm_core(
    const __nv_bfloat16* __restrict__ Ah, const __nv_bfloat16* __restrict__ Al,
    const __nv_bfloat16* __restrict__ Wh, const __nv_bfloat16* __restrict__ Wl,
    uint32_t sb, int m0, int n0, int tid, float acc[4][4][4])
{
    const int lane = tid & 31;
    const int wid  = tid >> 5;
    const int wm   = wid >> 2;
    const int wn   = wid & 3;
    const int g    = lane >> 2;
    const int t4   = lane & 3;
    const int lr0 = tid >> 2;
    const int lc0 = (tid & 3) * 8;       // element offset of this thread's 16-B chunk

#pragma unroll
    for (int mt = 0; mt < 4; mt++)
#pragma unroll
        for (int nt = 0; nt < 4; nt++)
#pragma unroll
            for (int q = 0; q < 4; q++) acc[mt][nt][q] = 0.f;

    auto load_tile = [&](int buf, int k0) {
        uint32_t base = sb + buf * BUF_B;
#pragma unroll
        for (int it = 0; it < 2; it++) {
            int r = lr0 + it * 64;
            uint32_t soff = (uint32_t)(r * SA + lc0) * 2;
            size_t ga = (size_t)(m0 + r) * DMODEL + k0 + lc0;
            size_t gb = (size_t)(n0 + r) * DMODEL + k0 + lc0;
            cp_async16(base + 0 * TILE_B + soff, Ah + ga);
            cp_async16(base + 1 * TILE_B + soff, Al + ga);
            cp_async16(base + 2 * TILE_B + soff, Wh + gb);
            cp_async16(base + 3 * TILE_B + soff, Wl + gb);
        }
        CP_COMMIT();
    };

    load_tile(0, 0);

    const int NT = DMODEL / 32;
    for (int kt = 0; kt < NT; kt++) {
        const int buf = kt & 1;
        if (kt + 1 < NT) {
            load_tile(buf ^ 1, (kt + 1) * 32);
            CP_WAIT(1);
        } else {
            CP_WAIT(0);
        }
        __syncthreads();

        const uint32_t bA = sb + buf * BUF_B;
        const uint32_t bB = bA + 2 * TILE_B;

#pragma unroll
        for (int s = 0; s < 2; s++) {
            const uint32_t koff = (uint32_t)(s * 32 + t4 * 8);   // bytes within row
            // B fragments (resident): one LDS.64 each gives {b0, b1}
            uint2 bhv[4], blv[4];
#pragma unroll
            for (int nt = 0; nt < 4; nt++) {
                int n = wn * 32 + nt * 8 + g;
                uint32_t o = bB + (uint32_t)n * (SA * 2) + koff;
                bhv[nt] = lds64(o);
                blv[nt] = lds64(o + TILE_B);
            }
            // A fragments streamed per mt: rows g and g+8, hi and lo
#pragma unroll
            for (int mt = 0; mt < 4; mt++) {
                int row = wm * 64 + mt * 16 + g;
                uint32_t oa = bA + (uint32_t)row * (SA * 2) + koff;
                uint2 h0 = lds64(oa);
                uint2 h1 = lds64(oa + 8 * SA * 2);
                uint2 l0 = lds64(oa + TILE_B);
                uint2 l1 = lds64(oa + TILE_B + 8 * SA * 2);
                uint32_t ah[4] = { h0.x, h1.x, h0.y, h1.y };
                uint32_t al[4] = { l0.x, l1.x, l0.y, l1.y };
#pragma unroll
                for (int nt = 0; nt < 4; nt++) {
                    uint32_t bb[2] = { bhv[nt].x, bhv[nt].y };
                    uint32_t cc[2] = { blv[nt].x, blv[nt].y };
                    mma16816(acc[mt][nt], ah, bb);
                    mma16816(acc[mt][nt], ah, cc);
                    mma16816(acc[mt][nt], al, bb);
                }
            }
        }
        __syncthreads();
    }
}

// ---------------------------------------------------------------------------
// QKV projection GEMM (grid.z in {0=Q, 1=K, 2=V}); epilogues write NORMAL
// layouts (consumed by attention).
// ---------------------------------------------------------------------------
struct GemmZP {
    const __nv_bfloat16 *Ah[3], *Al[3], *Wh[3], *Wl[3];
    const float* bias[3];
    __nv_bfloat16 *Ch[3], *Cl[3];
    float scale[3];
    int mode[3];
};

__global__ __launch_bounds__(256, 2) void gemm_qkv_kernel(GemmZP p)
{
    extern __shared__ __align__(128) char smem[];
    const uint32_t sb = smem_u32(smem);
    const int z = blockIdx.z;
    const int tid = threadIdx.x;
    const int lane = tid & 31;
    const int wid  = tid >> 5;
    const int wm = wid >> 2, wn = wid & 3;
    const int g = lane >> 2, t4 = lane & 3;
    const int m0 = blockIdx.y * 128;
    const int n0 = blockIdx.x * 128;

    float acc[4][4][4];
    gemm_core(p.Ah[z], p.Al[z], p.Wh[z], p.Wl[z], sb, m0, n0, tid, acc);

    const float* bias = p.bias[z];
    __nv_bfloat16* Ch = p.Ch[z];
    __nv_bfloat16* Cl = p.Cl[z];
    const float scale = p.scale[z];
    const int mode = p.mode[z];

#pragma unroll
    for (int mt = 0; mt < 4; mt++) {
        int row0 = m0 + wm * 64 + mt * 16 + g;
#pragma unroll
        for (int nt = 0; nt < 4; nt++) {
            int col = n0 + wn * 32 + nt * 8 + t4 * 2;
            float2 bv = *reinterpret_cast<const float2*>(bias + col);
            float v[2][2];
            v[0][0] = (acc[mt][nt][0] + bv.x) * scale;
            v[0][1] = (acc[mt][nt][1] + bv.y) * scale;
            v[1][0] = (acc[mt][nt][2] + bv.x) * scale;
            v[1][1] = (acc[mt][nt][3] + bv.y) * scale;
            int h = col >> 6, d = col & 63;
#pragma unroll
            for (int rr = 0; rr < 2; rr++) {
                int row = row0 + rr * 8;
                int b = row >> 11, s = row & 2047;
                int bh = b * HEADS + h;
                __nv_bfloat16 h0, h1, l0, l1;
                split1(v[rr][0], h0, l0);
                split1(v[rr][1], h1, l1);
                if (mode == 1) {
                    size_t off = ((size_t)bh * SEQ + s) * DK + d;
                    __nv_bfloat162 hp = __halves2bfloat162(h0, h1);
                    __nv_bfloat162 lp = __halves2bfloat162(l0, l1);
                    *reinterpret_cast<uint32_t*>(Ch + off) = *reinterpret_cast<uint32_t*>(&hp);
                    *reinterpret_cast<uint32_t*>(Cl + off) = *reinterpret_cast<uint32_t*>(&lp);
                } else {
                    size_t o0 = ((size_t)bh * DK + d) * SEQ + s;
                    size_t o1 = ((size_t)bh * DK + d + 1) * SEQ + s;
                    Ch[o0] = h0; Ch[o1] = h1;
                    Cl[o0] = l0; Cl[o1] = l1;
                }
            }
        }
    }
}

// ---------------------------------------------------------------------------
// Output projection GEMM (fp32 out)
// ---------------------------------------------------------------------------
__global__ __launch_bounds__(256, 2) void gemm_o_kernel(
    const __nv_bfloat16* __restrict__ Ah, const __nv_bfloat16* __restrict__ Al,
    const __nv_bfloat16* __restrict__ Wh, const __nv_bfloat16* __restrict__ Wl,
    const float* __restrict__ bias, float* __restrict__ Cf)
{
    extern __shared__ __align__(128) char smem[];
    const uint32_t sb = smem_u32(smem);
    const int tid = threadIdx.x;
    const int lane = tid & 31;
    const int wid  = tid >> 5;
    const int wm = wid >> 2, wn = wid & 3;
    const int g = lane >> 2, t4 = lane & 3;
    const int m0 = blockIdx.y * 128;
    const int n0 = blockIdx.x * 128;

    float acc[4][4][4];
    gemm_core(Ah, Al, Wh, Wl, sb, m0, n0, tid, acc);

#pragma unroll
    for (int mt = 0; mt < 4; mt++) {
        int row0 = m0 + wm * 64 + mt * 16 + g;
#pragma unroll
        for (int nt = 0; nt < 4; nt++) {
            int col = n0 + wn * 32 + nt * 8 + t4 * 2;
            float2 bv = *reinterpret_cast<const float2*>(bias + col);
            *reinterpret_cast<float2*>(Cf + (size_t)row0 * DMODEL + col) =
                make_float2(acc[mt][nt][0] + bv.x, acc[mt][nt][1] + bv.y);
            *reinterpret_cast<float2*>(Cf + (size_t)(row0 + 8) * DMODEL + col) =
                make_float2(acc[mt][nt][2] + bv.x, acc[mt][nt][3] + bv.y);
        }
    }
}

// ---------------------------------------------------------------------------
// Tensor-core flash attention (UNCHANGED mainloop from R12, best known).
// Only the epilogue's Sh/Sl writes use the permuted-block index (gemm_o input).
// ---------------------------------------------------------------------------
#define ATT_SA    72
#define ATT_TILE  (64 * ATT_SA * 2)        // 9216 B
#define ATT_BUF   (4 * ATT_TILE)           // 36864 B
#define ATT_QT    (128 * ATT_SA * 2)       // 18432 B
#define ATT_CH0   (2 * ATT_QT)             // 36864
#define ATT_SMEM  (ATT_CH0 + 2 * ATT_BUF)  // 110592 B

__global__ __launch_bounds__(128, 2) void attn_mma_kernel(
    float* __restrict__ scores,
    __nv_bfloat16* __restrict__ Ao_h, __nv_bfloat16* __restrict__ Ao_l)
{
    extern __shared__ __align__(128) char asmem[];
    const uint32_t sb = smem_u32(asmem);
    const uint32_t sbQ  = sb;
    const uint32_t sbQl = sb + ATT_QT;

    const int tid  = threadIdx.x;
    const int lane = tid & 31;
    const int wid  = tid >> 5;            // 0..3
    const int g    = lane >> 2;
    const int t4   = lane & 3;

    const int bh = blockIdx.y;
    const int q0 = blockIdx.x * 128;
    const int qrl = wid * 32;

#pragma unroll
    for (int it = 0; it < 8; it++) {
        int idx = tid + it * 128;
        int row = idx >> 3, c8 = idx & 7;
        uint32_t so = (uint32_t)row * (ATT_SA * 2) + c8 * 16;
        size_t gq = ((size_t)bh * SEQ + q0 + row) * DK + c8 * 8;
        cp_async16(sbQ + so, g_Qh + gq);
        cp_async16(sbQl + so, g_Ql + gq);
    }
    CP_COMMIT();

    float o[2][8][4];
#pragma unroll
    for (int mt = 0; mt < 2; mt++)
#pragma unroll
        for (int dt = 0; dt < 8; dt++)
#pragma unroll
            for (int q = 0; q < 4; q++) o[mt][dt][q] = 0.f;
    float mrow[2][2] = {{-INFINITY, -INFINITY}, {-INFINITY, -INFINITY}};
    float lrow[2][2] = {{0.f, 0.f}, {0.f, 0.f}};

    auto load_chunk = [&](int buf, int kt) {
        uint32_t base = sb + ATT_CH0 + buf * ATT_BUF;
#pragma unroll
        for (int it = 0; it < 4; it++) {
            int idx = tid + it * 128;
            int row = idx >> 3, c8 = idx & 7;
            uint32_t so = (uint32_t)row * (ATT_SA * 2) + c8 * 16;
            size_t gk = ((size_t)bh * SEQ + kt * 64 + row) * DK + c8 * 8;
            cp_async16(base + so, g_Kh + gk);
            cp_async16(base + ATT_TILE + so, g_Kl + gk);
            size_t gv = ((size_t)bh * DK + row) * SEQ + kt * 64 + c8 * 8;
            cp_async16(base + 2 * ATT_TILE + so, g_Vh + gv);
            cp_async16(base + 3 * ATT_TILE + so, g_Vl + gv);
        }
        CP_COMMIT();
    };

    load_chunk(0, 0);

    const int NCH = SEQ / 64;
    for (int kt = 0; kt < NCH; kt++) {
        const int buf = kt & 1;
        if (kt + 1 < NCH) {
            load_chunk(buf ^ 1, kt + 1);
            CP_WAIT(1);
        } else {
            CP_WAIT(0);
        }
        __syncthreads();

        const uint32_t bK  = sb + ATT_CH0 + buf * ATT_BUF;
        const uint32_t bKl = bK + ATT_TILE;
        const uint32_t bV  = bK + 2 * ATT_TILE;
        const uint32_t bVl = bK + 3 * ATT_TILE;

        float s[2][8][4];
#pragma unroll
        for (int mt = 0; mt < 2; mt++)
#pragma unroll
            for (int nt = 0; nt < 8; nt++)
#pragma unroll
                for (int q = 0; q < 4; q++) s[mt][nt][q] = 0.f;
#pragma unroll
        for (int kf = 0; kf < 4; kf++) {
            uint32_t qc = (uint32_t)(kf * 8 + t4) * 4;
            uint32_t q0off = (uint32_t)(qrl + g) * (ATT_SA * 2) + qc;
            uint32_t q1off = (uint32_t)(qrl + 16 + g) * (ATT_SA * 2) + qc;
            uint32_t qh0[4], ql0[4], qh1[4], ql1[4];
            qh0[0] = lds32(sbQ + q0off);
            qh0[1] = lds32(sbQ + q0off + 8 * ATT_SA * 2);
            qh0[2] = lds32(sbQ + q0off + 16);
            qh0[3] = lds32(sbQ + q0off + 8 * ATT_SA * 2 + 16);
            ql0[0] = lds32(sbQl + q0off);
            ql0[1] = lds32(sbQl + q0off + 8 * ATT_SA * 2);
            ql0[2] = lds32(sbQl + q0off + 16);
            ql0[3] = lds32(sbQl + q0off + 8 * ATT_SA * 2 + 16);
            qh1[0] = lds32(sbQ + q1off);
            qh1[1] = lds32(sbQ + q1off + 8 * ATT_SA * 2);
            qh1[2] = lds32(sbQ + q1off + 16);
            qh1[3] = lds32(sbQ + q1off + 8 * ATT_SA * 2 + 16);
            ql1[0] = lds32(sbQl + q1off);
            ql1[1] = lds32(sbQl + q1off + 8 * ATT_SA * 2);
            ql1[2] = lds32(sbQl + q1off + 16);
            ql1[3] = lds32(sbQl + q1off + 8 * ATT_SA * 2 + 16);
#pragma unroll
            for (int nt = 0; nt < 8; nt++) {
                uint32_t off = ((uint32_t)(nt * 8 + g) * ATT_SA + kf * 16 + t4 * 2) * 2;
                uint32_t kbh[2] = { lds32(bK + off),  lds32(bK + off + 16) };
                uint32_t kbl[2] = { lds32(bKl + off), lds32(bKl + off + 16) };
                mma16816(s[0][nt], qh0, kbh);
                mma16816(s[0][nt], qh0, kbl);
                mma16816(s[0][nt], ql0, kbh);
                mma16816(s[1][nt], qh1, kbh);
                mma16816(s[1][nt], qh1, kbl);
                mma16816(s[1][nt], ql1, kbh);
            }
        }

#pragma unroll
        for (int mt = 0; mt < 2; mt++) {
#pragma unroll
            for (int hh = 0; hh < 2; hh++) {
                float mx = -INFINITY;
#pragma unroll
                for (int nt = 0; nt < 8; nt++)
                    mx = fmaxf(mx, fmaxf(s[mt][nt][2 * hh], s[mt][nt][2 * hh + 1]));
                mx = fmaxf(mx, __shfl_xor_sync(0xffffffffu, mx, 1));
                mx = fmaxf(mx, __shfl_xor_sync(0xffffffffu, mx, 2));
                float mnew = fmaxf(mrow[mt][hh], mx);
                float sc = __expf(mrow[mt][hh] - mnew);
                mrow[mt][hh] = mnew;
                float rs = 0.f;
#pragma unroll
                for (int nt = 0; nt < 8; nt++) {
                    s[mt][nt][2 * hh]     = __expf(s[mt][nt][2 * hh] - mnew);
                    s[mt][nt][2 * hh + 1] = __expf(s[mt][nt][2 * hh + 1] - mnew);
                    rs += s[mt][nt][2 * hh] + s[mt][nt][2 * hh + 1];
                }
                rs += __shfl_xor_sync(0xffffffffu, rs, 1);
                rs += __shfl_xor_sync(0xffffffffu, rs, 2);
                lrow[mt][hh] = lrow[mt][hh] * sc + rs;
#pragma unroll
                for (int dt = 0; dt < 8; dt++) {
                    o[mt][dt][2 * hh]     *= sc;
                    o[mt][dt][2 * hh + 1] *= sc;
                }
            }
        }

        uint32_t ph[2][4][4], pl[2][4][4];
#pragma unroll
        for (int mt = 0; mt < 2; mt++) {
#pragma unroll
            for (int kf = 0; kf < 4; kf++) {
#pragma unroll
                for (int half = 0; half < 2; half++) {
                    const float* sv = s[mt][2 * kf + half];
                    __nv_bfloat16 h0, h1, h2, h3, l0, l1, l2, l3;
                    split1(sv[0], h0, l0); split1(sv[1], h1, l1);
                    split1(sv[2], h2, l2); split1(sv[3], h3, l3);
                    __nv_bfloat162 a, b, c, d;
                    a = __halves2bfloat162(h0, h1); b = __halves2bfloat162(h2, h3);
                    c = __halves2bfloat162(l0, l1); d = __halves2bfloat162(l2, l3);
                    ph[mt][kf][2 * half + 0] = *reinterpret_cast<uint32_t*>(&a);
                    ph[mt][kf][2 * half + 1] = *reinterpret_cast<uint32_t*>(&b);
                    pl[mt][kf][2 * half + 0] = *reinterpret_cast<uint32_t*>(&c);
                    pl[mt][kf][2 * half + 1] = *reinterpret_cast<uint32_t*>(&d);
                }
            }
        }

#pragma unroll
        for (int kf = 0; kf < 4; kf++) {
#pragma unroll
            for (int dt = 0; dt < 8; dt++) {
                uint32_t off = ((uint32_t)(dt * 8 + g) * ATT_SA + kf * 16 + t4 * 2) * 2;
                uint32_t vbh[2] = { lds32(bV + off),  lds32(bV + off + 16) };
                uint32_t vbl[2] = { lds32(bVl + off), lds32(bVl + off + 16) };
                mma16816(o[0][dt], ph[0][kf], vbh);
                mma16816(o[0][dt], ph[0][kf], vbl);
                mma16816(o[0][dt], pl[0][kf], vbh);
                mma16816(o[1][dt], ph[1][kf], vbh);
                mma16816(o[1][dt], ph[1][kf], vbl);
                mma16816(o[1][dt], pl[1][kf], vbh);
            }
        }
        __syncthreads();
    }

    // ---- epilogue: fp32 scores (normal d) + permuted hi/lo split for gemm_o ----
    const int b = bh >> 4, hhd = bh & 15;
#pragma unroll
    for (int mt = 0; mt < 2; mt++) {
#pragma unroll
        for (int hh = 0; hh < 2; hh++) {
            float inv = 1.f / lrow[mt][hh];
            int srow = q0 + qrl + mt * 16 + g + hh * 8;
#pragma unroll
            for (int dt = 0; dt < 8; dt++) {
                int d = dt * 8 + t4 * 2;
                float v0 = o[mt][dt][2 * hh] * inv;
                float v1 = o[mt][dt][2 * hh + 1] * inv;
                *reinterpret_cast<float2*>(
                    scores + ((size_t)bh * SEQ + srow) * DK + d) = make_float2(v0, v1);
                __nv_bfloat16 h0, h1, l0, l1;
                split1(v0, h0, l0); split1(v1, h1, l1);
                __nv_bfloat162 hp = __halves2bfloat162(h0, h1);
                __nv_bfloat162 lp = __halves2bfloat162(l0, l1);
                // permuted-block position for the (k{d}, k{d+1}) pair
                int dperm = (d & ~15) + 4 * t4 + 2 * (dt & 1);
                size_t mi = ((size_t)(b * SEQ + srow)) * DMODEL + hhd * DK + dperm;
                *reinterpret_cast<uint32_t*>(Ao_h + mi) = *reinterpret_cast<uint32_t*>(&hp);
                *reinterpret_cast<uint32_t*>(Ao_l + mi) = *reinterpret_cast<uint32_t*>(&lp);
            }
        }
    }
}

// ---------------------------------------------------------------------------
extern "C" void kernel_launch(void* const* d_in, const int* in_sizes, int n_in,
                              void* d_out, int out_size)
{
    const float* query = (const float*)d_in[0];
    const float* key   = (const float*)d_in[1];
    const float* value = (const float*)d_in[2];
    const float* Wq = (const float*)d_in[3];
    const float* bq = (const float*)d_in[4];
    const float* Wk = (const float*)d_in[5];
    const float* bk = (const float*)d_in[6];
    const float* Wv = (const float*)d_in[7];
    const float* bv = (const float*)d_in[8];
    const float* Wo = (const float*)d_in[9];
    const float* bo = (const float*)d_in[10];

    float* out    = (float*)d_out;
    float* scores = (float*)d_out + QKV_ELEMS;

    __nv_bfloat16 *qh, *ql, *kh, *kl, *vh, *vl, *sh, *sl;
    __nv_bfloat16 *axh, *axl, *wsh, *wsl;
    cudaGetSymbolAddress((void**)&qh, g_Qh);
    cudaGetSymbolAddress((void**)&ql, g_Ql);
    cudaGetSymbolAddress((void**)&kh, g_Kh);
    cudaGetSymbolAddress((void**)&kl, g_Kl);
    cudaGetSymbolAddress((void**)&vh, g_Vh);
    cudaGetSymbolAddress((void**)&vl, g_Vl);
    cudaGetSymbolAddress((void**)&sh, g_Sh);
    cudaGetSymbolAddress((void**)&sl, g_Sl);
    cudaGetSymbolAddress((void**)&axh, g_Axh);
    cudaGetSymbolAddress((void**)&axl, g_Axl);
    cudaGetSymbolAddress((void**)&wsh, g_Wsh);
    cudaGetSymbolAddress((void**)&wsl, g_Wsl);

    const size_t ASTRIDE = (size_t)MROWS * DMODEL;
    const size_t WSTRIDE = (size_t)DMODEL * DMODEL;

    cudaFuncSetAttribute(gemm_qkv_kernel,
                         cudaFuncAttributeMaxDynamicSharedMemorySize, GEMM_SMEM);
    cudaFuncSetAttribute(gemm_o_kernel,
                         cudaFuncAttributeMaxDynamicSharedMemorySize, GEMM_SMEM);
    cudaFuncSetAttribute(attn_mma_kernel,
                         cudaFuncAttributeMaxDynamicSharedMemorySize, ATT_SMEM);

    const int nA16 = MROWS * DMODEL / 16;    // 262144
    const int nW16 = DMODEL * DMODEL / 16;   // 65536

    // 0) no-op so ncu's captured slot (#4) lands on gemm_qkv_kernel
    warmup_noop<<<1, 32>>>();

    // 1) split q/k/v inputs (permuted blocks)
    {
        SplitP p{};
        p.src[0] = query; p.src[1] = key; p.src[2] = value;
        for (int z = 0; z < 3; z++) {
            p.hi[z] = axh + z * ASTRIDE;
            p.lo[z] = axl + z * ASTRIDE;
        }
        dim3 grid(nA16 / 256, 3);
        split_many_kernel<<<grid, 256>>>(p, nA16);
    }
    // 2) split weights (permuted blocks)
    {
        SplitP p{};
        p.src[0] = Wq; p.src[1] = Wk; p.src[2] = Wv; p.src[3] = Wo;
        for (int z = 0; z < 4; z++) {
            p.hi[z] = wsh + z * WSTRIDE;
            p.lo[z] = wsl + z * WSTRIDE;
        }
        dim3 grid(nW16 / 256, 4);
        split_many_kernel<<<grid, 256>>>(p, nW16);
    }
    // 3) Q/K/V projections
    {
        GemmZP p{};
        const float* biases[3] = {bq, bk, bv};
        __nv_bfloat16* chs[3] = {qh, kh, vh};
        __nv_bfloat16* cls[3] = {ql, kl, vl};
        for (int z = 0; z < 3; z++) {
            p.Ah[z] = axh + z * ASTRIDE;
            p.Al[z] = axl + z * ASTRIDE;
            p.Wh[z] = wsh + z * WSTRIDE;
            p.Wl[z] = wsl + z * WSTRIDE;
            p.bias[z] = biases[z];
            p.Ch[z] = chs[z];
            p.Cl[z] = cls[z];
        }
        p.scale[0] = 0.125f; p.scale[1] = 1.0f; p.scale[2] = 1.0f;
        p.mode[0] = 1; p.mode[1] = 1; p.mode[2] = 2;
        dim3 grid(DMODEL / 128, MROWS / 128, 3);
        gemm_qkv_kernel<<<grid, 256, GEMM_SMEM>>>(p);
    }
    // 4) attention
    {
        dim3 grid(SEQ / 128, BS * HEADS);
        attn_mma_kernel<<<grid, 128, ATT_SMEM>>>(scores, sh, sl);
    }
    // 5) output projection
    {
        dim3 grid(DMODEL / 128, MROWS / 128);
        gemm_o_kernel<<<grid, 256, GEMM_SMEM>>>(sh, sl, wsh + 3 * WSTRIDE,
                                                wsl + 3 * WSTRIDE, bo, out);
    }
}